// round 14
// baseline (speedup 1.0000x reference)
#include <cuda_runtime.h>
#include <cuda_bf16.h>
#include <math.h>

#define BB 256
#define HH 512
#define CC 512
#define NL 128
#define TT 23
#define LSEQ 24
#define VV 64
#define BH (BB*HH)
#define NTOK (TT*BB)
#define KC 32
#define ASTR 40

typedef unsigned long long u64;
typedef unsigned int u32;

__device__ __forceinline__ void MMA16816(float &d0, float &d1, float &d2, float &d3,
                                         u32 a0, u32 a1, u32 a2, u32 a3,
                                         u32 b0, u32 b1){
  asm volatile("mma.sync.aligned.m16n8k16.row.col.f32.bf16.bf16.f32 "
               "{%0,%1,%2,%3},{%4,%5,%6,%7},{%8,%9},{%0,%1,%2,%3};"
               : "+f"(d0), "+f"(d1), "+f"(d2), "+f"(d3)
               : "r"(a0), "r"(a1), "r"(a2), "r"(a3), "r"(b0), "r"(b1));
}
__device__ __forceinline__ u32 BF2U(__nv_bfloat162 v){ return *reinterpret_cast<u32*>(&v); }
__device__ __forceinline__ void FMA2(u64 &d, u64 a, u64 b){
  asm("fma.rn.f32x2 %0, %1, %2, %0;" : "+l"(d) : "l"(a), "l"(b));
}
__device__ __forceinline__ u64 PACK2(float x, float y){
  u64 r; asm("mov.b64 %0, {%1, %2};" : "=l"(r) : "f"(x), "f"(y)); return r;
}
__device__ __forceinline__ float2 UNPK(u64 v){
  float2 r; asm("mov.b64 {%0, %1}, %2;" : "=f"(r.x), "=f"(r.y) : "l"(v)); return r;
}

// ---------------- static scratch ----------------
__device__ __nv_bfloat16 g_Wsh[(size_t)BB*NL*HH];
__device__ __nv_bfloat16 g_ench[(size_t)BB*CC*NL];
__device__ __nv_bfloat16 g_w_aWw[HH*CC];
__device__ __nv_bfloat16 g_w_aUw[HH*HH];
__device__ __nv_bfloat16 g_w_fcw[HH*(CC+HH)];
__device__ __nv_bfloat16 g_w_g0wih[3*HH*2*HH];
__device__ __nv_bfloat16 g_w_g0whh[3*HH*HH];
__device__ __nv_bfloat16 g_w_g1wih[3*HH*HH];
__device__ __nv_bfloat16 g_w_g1whh[3*HH*HH];
__device__ float g_xg[(size_t)TT*BB*3*HH];
__device__ float g_xs[(size_t)TT*BH];
__device__ float g_ys[(size_t)TT*BH];
__device__ float g_y0[BH];
__device__ float g_h0buf[2][BH];
__device__ float g_h1buf[2][BH];
__device__ float g_gp0[4][(size_t)BB*3*HH];
__device__ float g_gp1[4][(size_t)BB*3*HH];
__device__ float g_fp[4][BH];
__device__ float g_Up[2][BH];
__device__ float g_ctx[BH];
__device__ float g_lg[2][(size_t)NTOK*VV];
__device__ float g_nll[NTOK];
__device__ float g_msk[NTOK];

// ---------------- init / embed / convert ----------------
__global__ void k_inith(const float* __restrict__ init_state,
                        float* __restrict__ h0, float* __restrict__ h1){
  int idx = blockIdx.x*blockDim.x + threadIdx.x;
  if (idx < BH){
    int j = idx & (HH-1);
    h0[idx] = init_state[j];
    h1[idx] = init_state[HH + j];
  }
}

__global__ void k_embed(const float* __restrict__ emb, const int* __restrict__ seq,
                        float* __restrict__ xs){
  int idx = blockIdx.x*blockDim.x + threadIdx.x;
  if (idx < TT*BH){
    int h = idx & (HH-1);
    int r = idx >> 9;
    int b = r & (BB-1);
    int t = r >> 8;
    int tok = seq[b*LSEQ + t];
    xs[idx] = emb[(size_t)tok*HH + h];
  }
}

__global__ void k_tobf16(const float* __restrict__ in, __nv_bfloat16* __restrict__ out, int n4){
  int idx = blockIdx.x*blockDim.x + threadIdx.x;
  if (idx < n4){
    float4 v = *(const float4*)&in[(size_t)idx*4];
    *(__nv_bfloat162*)&out[(size_t)idx*4]   = __floats2bfloat162_rn(v.x, v.y);
    *(__nv_bfloat162*)&out[(size_t)idx*4+2] = __floats2bfloat162_rn(v.z, v.w);
  }
}

// ============ 64x128 mma frag pattern (8 warps of 32x32) ============
#define MMA_FRAGS(AtP, WtP)                                                    \
  _Pragma("unroll")                                                            \
  for (int k16 = 0; k16 < KC; k16 += 16){                                      \
    u32 af[2][4]; u32 bfv[4][2];                                               \
    _Pragma("unroll")                                                          \
    for (int mt = 0; mt < 2; mt++){                                            \
      int r = wm + mt*16 + gid;                                                \
      af[mt][0] = *(const u32*)&(AtP)[r*ASTR      + k16 + tig*2];              \
      af[mt][1] = *(const u32*)&(AtP)[(r+8)*ASTR  + k16 + tig*2];              \
      af[mt][2] = *(const u32*)&(AtP)[r*ASTR      + k16 + tig*2 + 8];          \
      af[mt][3] = *(const u32*)&(AtP)[(r+8)*ASTR  + k16 + tig*2 + 8];          \
    }                                                                          \
    _Pragma("unroll")                                                          \
    for (int nt = 0; nt < 4; nt++){                                            \
      int r = wn + nt*8 + gid;                                                 \
      bfv[nt][0] = *(const u32*)&(WtP)[r*ASTR + k16 + tig*2];                  \
      bfv[nt][1] = *(const u32*)&(WtP)[r*ASTR + k16 + tig*2 + 8];              \
    }                                                                          \
    _Pragma("unroll")                                                          \
    for (int mt = 0; mt < 2; mt++)                                             \
      _Pragma("unroll")                                                        \
      for (int nt = 0; nt < 4; nt++)                                           \
        MMA16816(acc[mt][nt][0], acc[mt][nt][1], acc[mt][nt][2], acc[mt][nt][3],\
                 af[mt][0], af[mt][1], af[mt][2], af[mt][3],                   \
                 bfv[nt][0], bfv[nt][1]);                                      \
  }

// ---------------- generic mma GEMM (2 sets, K-sliced partials) ----------------
__global__ void __launch_bounds__(256) k_mmT(
    const float* __restrict__ A0, int wA0,
    const __nv_bfloat16* __restrict__ W0, int s0, int o0,
    const float* __restrict__ A1, int wA1,
    const __nv_bfloat16* __restrict__ W1, int s1, int o1,
    int zPerSet, int kSlice, float* __restrict__ Cb, int ldc){
  __shared__ __align__(16) __nv_bfloat16 At[2][64*ASTR];
  __shared__ __align__(16) __nv_bfloat16 Wt[2][128*ASTR];
  int z = blockIdx.z;
  int set = z / zPerSet;
  int kb = (z - set*zPerSet) * kSlice;
  const float* A = set ? A1 : A0;
  const __nv_bfloat16* W = set ? W1 : W0;
  int wA = set ? wA1 : wA0;
  int s  = set ? s1 : s0;
  int o  = set ? o1 : o0;
  int M = gridDim.x * 64;
  float* C = Cb + (size_t)z * M * ldc;

  int m0 = blockIdx.x*64, n0 = blockIdx.y*128;
  int tid = threadIdx.x;
  int warp = tid >> 5, lane = tid & 31;
  int wm = (warp & 1)*32, wn = (warp >> 1)*32;
  int gid = lane >> 2, tig = lane & 3;
  float acc[2][4][4] = {};

  float4 ra[2]; uint4 rw[2];
  auto loadT = [&](int t){
    int kc = kb + t*KC;
    #pragma unroll
    for (int i=0;i<2;i++){
      int idx = tid + i*256;
      int r = idx >> 3, k4 = (idx & 7)*4;
      ra[i] = *(const float4*)&A[(size_t)(m0+r)*wA + kc + k4];
      int rr = idx >> 2, k8 = (idx & 3)*8;
      rw[i] = *(const uint4*)&W[(size_t)(n0+rr)*s + o + kc + k8];
    }
  };
  auto storeT = [&](int buf){
    #pragma unroll
    for (int i=0;i<2;i++){
      int idx = tid + i*256;
      int r = idx >> 3, k4 = (idx & 7)*4;
      u32 p0 = BF2U(__floats2bfloat162_rn(ra[i].x, ra[i].y));
      u32 p1 = BF2U(__floats2bfloat162_rn(ra[i].z, ra[i].w));
      *(uint2*)&At[buf][r*ASTR + k4] = make_uint2(p0, p1);
      int rr = idx >> 2, k8 = (idx & 3)*8;
      *(uint4*)&Wt[buf][rr*ASTR + k8] = rw[i];
    }
  };

  int ntc = kSlice / KC;
  loadT(0); storeT(0); __syncthreads();
  for (int t=0;t<ntc;t++){
    int buf = t & 1;
    if (t+1 < ntc) loadT(t+1);
    MMA_FRAGS(At[buf], Wt[buf])
    if (t+1 < ntc) storeT((t+1)&1);
    __syncthreads();
  }

  #pragma unroll
  for (int mt=0;mt<2;mt++){
    #pragma unroll
    for (int nt=0;nt<4;nt++){
      int m = m0 + wm + mt*16 + gid;
      int n = n0 + wn + nt*8 + tig*2;
      *(float2*)&C[(size_t)m*ldc + n]     = make_float2(acc[mt][nt][0], acc[mt][nt][1]);
      *(float2*)&C[(size_t)(m+8)*ldc + n] = make_float2(acc[mt][nt][2], acc[mt][nt][3]);
    }
  }
}

// ---------------- Ws GEMM (bf16 ench A, bf16 out) ----------------
__global__ void __launch_bounds__(256) k_wsT(
    const __nv_bfloat16* __restrict__ ench,
    const __nv_bfloat16* __restrict__ Wwb,
    const float* __restrict__ Wb,
    __nv_bfloat16* __restrict__ Wsh){
  __shared__ __align__(16) __nv_bfloat16 At2[2][64*ASTR];
  __shared__ __align__(16) __nv_bfloat16 Wt2[2][128*ASTR];
  int m0 = blockIdx.x*64;
  int b = m0 >> 7, l0 = m0 & 127;
  int n0 = blockIdx.y*128;
  int tid = threadIdx.x;
  int warp = tid >> 5, lane = tid & 31;
  int wm = (warp & 1)*32, wn = (warp >> 1)*32;
  int gid = lane >> 2, tig = lane & 3;
  float acc[2][4][4] = {};

  uint4 raw; uint4 rw[2];
  int ak = tid >> 3, al8 = (tid & 7)*8;

  auto loadT = [&](int t){
    int kc = t*KC;
    raw = *(const uint4*)&ench[(size_t)b*CC*NL + (size_t)(kc+ak)*NL + l0 + al8];
    #pragma unroll
    for (int i=0;i<2;i++){
      int idx = tid + i*256;
      int rr = idx >> 2, k8 = (idx & 3)*8;
      rw[i] = *(const uint4*)&Wwb[(size_t)(n0+rr)*CC + kc + k8];
    }
  };
  auto storeT = [&](int buf){
    const __nv_bfloat16* src = (const __nv_bfloat16*)&raw;
    #pragma unroll
    for (int i=0;i<8;i++) At2[buf][(al8+i)*ASTR + ak] = src[i];
    #pragma unroll
    for (int i=0;i<2;i++){
      int idx = tid + i*256;
      int rr = idx >> 2, k8 = (idx & 3)*8;
      *(uint4*)&Wt2[buf][rr*ASTR + k8] = rw[i];
    }
  };

  loadT(0); storeT(0); __syncthreads();
  for (int t=0;t<16;t++){
    int buf = t & 1;
    if (t+1 < 16) loadT(t+1);
    MMA_FRAGS(At2[buf], Wt2[buf])
    if (t+1 < 16) storeT((t+1)&1);
    __syncthreads();
  }

  #pragma unroll
  for (int mt=0;mt<2;mt++){
    #pragma unroll
    for (int nt=0;nt<4;nt++){
      int m = m0 + wm + mt*16 + gid;
      int n = n0 + wn + nt*8 + tig*2;
      float2 bi = *(const float2*)&Wb[n];
      *(__nv_bfloat162*)&Wsh[(size_t)m*HH + n] =
          __floats2bfloat162_rn(acc[mt][nt][0]+bi.x, acc[mt][nt][1]+bi.y);
      *(__nv_bfloat162*)&Wsh[(size_t)(m+8)*HH + n] =
          __floats2bfloat162_rn(acc[mt][nt][2]+bi.x, acc[mt][nt][3]+bi.y);
    }
  }
}

// ---------------- logits GEMM (fp32, N=64, K-split 2) ----------------
__global__ void __launch_bounds__(256) k_g64(const float* __restrict__ A0, int wA0,
                                             const float* __restrict__ W0, int s0, int o0,
                                             float* __restrict__ C0, float* __restrict__ C1,
                                             int ldc){
  __shared__ __align__(16) float At[2][16][68];
  __shared__ __align__(16) float Wt[2][16][68];
  int z = blockIdx.z;
  int kbase = z*256;
  float* C = z ? C1 : C0;
  int m0 = blockIdx.x*64, n0 = blockIdx.y*64;
  int tid = threadIdx.x, tm = tid & 15, tn = tid >> 4;
  u64 acc[4][2] = {};
  float4 ra, rw;
  int mm = tid >> 2, k4 = (tid & 3)*4;

  auto loadT = [&](int t){
    int kc = kbase + t*16;
    ra = *(const float4*)&A0[(size_t)(m0+mm)*wA0 + kc + k4];
    rw = *(const float4*)&W0[(size_t)(n0+mm)*s0 + o0 + kc + k4];
  };
  auto storeT = [&](int buf){
    At[buf][k4+0][mm]=ra.x; At[buf][k4+1][mm]=ra.y; At[buf][k4+2][mm]=ra.z; At[buf][k4+3][mm]=ra.w;
    Wt[buf][k4+0][mm]=rw.x; Wt[buf][k4+1][mm]=rw.y; Wt[buf][k4+2][mm]=rw.z; Wt[buf][k4+3][mm]=rw.w;
  };

  loadT(0); storeT(0); __syncthreads();
  for (int t=0;t<16;t++){
    int buf = t & 1;
    if (t+1 < 16) loadT(t+1);
    #pragma unroll
    for (int kk=0;kk<16;kk++){
      float4 av = *(const float4*)&At[buf][kk][tm*4];
      ulonglong2 wv = *(const ulonglong2*)&Wt[buf][kk][tn*4];
      u64 a0=PACK2(av.x,av.x), a1=PACK2(av.y,av.y), a2=PACK2(av.z,av.z), a3=PACK2(av.w,av.w);
      FMA2(acc[0][0],a0,wv.x); FMA2(acc[0][1],a0,wv.y);
      FMA2(acc[1][0],a1,wv.x); FMA2(acc[1][1],a1,wv.y);
      FMA2(acc[2][0],a2,wv.x); FMA2(acc[2][1],a2,wv.y);
      FMA2(acc[3][0],a3,wv.x); FMA2(acc[3][1],a3,wv.y);
    }
    if (t+1 < 16) storeT((t+1)&1);
    __syncthreads();
  }
  #pragma unroll
  for (int mi=0;mi<4;mi++){
    int m = m0 + tm*4 + mi;
    #pragma unroll
    for (int h=0;h<2;h++){
      float2 p = UNPK(acc[mi][h]);
      int n = n0 + tn*4 + h*2;
      *(float2*)&C[(size_t)m*ldc + n] = make_float2(p.x, p.y);
    }
  }
}

// ---------------- GRU pointwise: combine 4 gate partials ----------------
__global__ void __launch_bounds__(256) k_pw(const float* __restrict__ P0,
                                            const float* __restrict__ P1,
                                            const float* __restrict__ P2,
                                            const float* __restrict__ P3,
                                            const float* __restrict__ xg,
                                            const float* __restrict__ hprev,
                                            const float* __restrict__ bih,
                                            const float* __restrict__ bhh,
                                            float* __restrict__ hnew){
  int idx = blockIdx.x*256 + threadIdx.x;
  int b = idx >> 9, j = idx & (HH-1);
  size_t r0 = (size_t)b*(3*HH);
  float gr = P0[r0+j] + P1[r0+j] + P2[r0+j] + P3[r0+j] + bih[j] + bhh[j];
  float gz = P0[r0+HH+j] + P1[r0+HH+j] + P2[r0+HH+j] + P3[r0+HH+j] + bih[HH+j] + bhh[HH+j];
  float gi = P0[r0+2*HH+j] + P1[r0+2*HH+j] + bih[2*HH+j];
  float gh = P2[r0+2*HH+j] + P3[r0+2*HH+j] + bhh[2*HH+j];
  if (xg){
    gr += xg[r0+j]; gz += xg[r0+HH+j]; gi += xg[r0+2*HH+j];
  }
  float r = 1.f/(1.f+expf(-gr));
  float z = 1.f/(1.f+expf(-gz));
  float n = tanhf(gi + r*gh);
  hnew[idx] = (1.f-z)*n + z*hprev[idx];
}

// ---------------- fc pointwise ----------------
__global__ void __launch_bounds__(256) k_pwfc(const float* __restrict__ F0,
                                              const float* __restrict__ F1,
                                              const float* __restrict__ F2,
                                              const float* __restrict__ F3,
                                              const float* __restrict__ fcb,
                                              float* __restrict__ y){
  int idx = blockIdx.x*256 + threadIdx.x;
  int j = idx & (HH-1);
  float v = F0[idx] + F1[idx] + F2[idx] + F3[idx] + fcb[j];
  y[idx] = fmaxf(v, 0.f);
}

// ---------------- attention (R12 version: 256 blocks x 256 threads) ----------------
__global__ void __launch_bounds__(256) k_attn(const __nv_bfloat16* __restrict__ Wsh,
                                              const __nv_bfloat16* __restrict__ ench,
                                              const float* __restrict__ UhA,
                                              const float* __restrict__ UhB,
                                              const float* __restrict__ aUb,
                                              const float* __restrict__ vw,
                                              const float* __restrict__ vb,
                                              float* __restrict__ ctx){
  __shared__ __align__(16) float us[HH];
  __shared__ __align__(16) float vs[HH];
  __shared__ __align__(16) float sc[NL];
  int b = blockIdx.x, tid = threadIdx.x;

  {
    float2 a = *(const float2*)&UhA[(size_t)b*HH + tid*2];
    float2 c = *(const float2*)&UhB[(size_t)b*HH + tid*2];
    float2 u = *(const float2*)&aUb[tid*2];
    us[tid*2]   = a.x + c.x + u.x;
    us[tid*2+1] = a.y + c.y + u.y;
    *(float2*)&vs[tid*2] = *(const float2*)&vw[tid*2];
  }
  __syncthreads();

  {
    int l = tid >> 1, half = tid & 1;
    const uint4* wp = (const uint4*)(Wsh + ((size_t)(b*NL + l))*HH + half*256);
    float s = 0.f;
    #pragma unroll 4
    for (int i=0;i<32;i++){
      uint4 q = wp[i];
      const __nv_bfloat162* h2 = (const __nv_bfloat162*)&q;
      int off = half*256 + i*8;
      float4 u0 = *(const float4*)&us[off];
      float4 u1 = *(const float4*)&us[off+4];
      float4 v0 = *(const float4*)&vs[off];
      float4 v1 = *(const float4*)&vs[off+4];
      float2 w0=__bfloat1622float2(h2[0]), w1=__bfloat1622float2(h2[1]);
      float2 w2=__bfloat1622float2(h2[2]), w3=__bfloat1622float2(h2[3]);
      s += fmaxf(w0.x+u0.x,0.f)*v0.x + fmaxf(w0.y+u0.y,0.f)*v0.y
         + fmaxf(w1.x+u0.z,0.f)*v0.z + fmaxf(w1.y+u0.w,0.f)*v0.w
         + fmaxf(w2.x+u1.x,0.f)*v1.x + fmaxf(w2.y+u1.y,0.f)*v1.y
         + fmaxf(w3.x+u1.z,0.f)*v1.z + fmaxf(w3.y+u1.w,0.f)*v1.w;
    }
    s += __shfl_xor_sync(0xffffffffu, s, 1);
    if (!half) sc[l] = s + vb[0];
  }
  __syncthreads();
  if (tid < 32){
    float m = -1e30f;
    for (int l = tid; l < NL; l += 32) m = fmaxf(m, sc[l]);
    #pragma unroll
    for (int o=16;o;o>>=1) m = fmaxf(m, __shfl_xor_sync(0xffffffffu,m,o));
    float s = 0.f;
    for (int l = tid; l < NL; l += 32){ float e = expf(sc[l]-m); sc[l] = e; s += e; }
    #pragma unroll
    for (int o=16;o;o>>=1) s += __shfl_xor_sync(0xffffffffu,s,o);
    float inv = 1.f/s;
    for (int l = tid; l < NL; l += 32) sc[l] *= inv;
  }
  __syncthreads();
  #pragma unroll
  for (int cc=0;cc<2;cc++){
    int c = tid + cc*256;
    const uint4* ep = (const uint4*)(ench + ((size_t)b*CC + c)*NL);
    float s = 0.f;
    #pragma unroll 4
    for (int i=0;i<16;i++){
      uint4 q = ep[i];
      const __nv_bfloat162* h2 = (const __nv_bfloat162*)&q;
      float4 a0 = *(const float4*)&sc[i*8];
      float4 a1 = *(const float4*)&sc[i*8+4];
      float2 e0=__bfloat1622float2(h2[0]), e1=__bfloat1622float2(h2[1]);
      float2 e2=__bfloat1622float2(h2[2]), e3=__bfloat1622float2(h2[3]);
      s += e0.x*a0.x + e0.y*a0.y + e1.x*a0.z + e1.y*a0.w
         + e2.x*a1.x + e2.y*a1.y + e3.x*a1.z + e3.y*a1.w;
    }
    ctx[(size_t)b*CC + c] = s;
  }
}

// ---------------- per-token NLL ----------------
__global__ void __launch_bounds__(256) k_nll(const float* __restrict__ LA,
                                             const float* __restrict__ LB,
                                             const float* __restrict__ clsb,
                                             const int* __restrict__ seq,
                                             float* __restrict__ nll,
                                             float* __restrict__ msk){
  int idx = blockIdx.x*256 + threadIdx.x;
  int t = idx >> 8, b = idx & 255;
  float lg[VV];
  const float4* pa = (const float4*)(LA + (size_t)idx*VV);
  const float4* pb = (const float4*)(LB + (size_t)idx*VV);
  float m = -1e30f;
  #pragma unroll
  for (int i=0;i<16;i++){
    float4 a = pa[i], c = pb[i];
    float4 d = *(const float4*)&clsb[i*4];
    lg[i*4+0] = a.x + c.x + d.x;
    lg[i*4+1] = a.y + c.y + d.y;
    lg[i*4+2] = a.z + c.z + d.z;
    lg[i*4+3] = a.w + c.w + d.w;
  }
  #pragma unroll
  for (int v=0;v<VV;v++) m = fmaxf(m, lg[v]);
  float se = 0.f;
  #pragma unroll
  for (int v=0;v<VV;v++) se += expf(lg[v]-m);
  int label = seq[b*LSEQ + t + 1];
  float lp = lg[label] - m - logf(se);
  bool mk = label > 0;
  nll[idx] = mk ? -lp : 0.f;
  msk[idx] = mk ? 1.f : 0.f;
}

// ---------------- deterministic final reduction ----------------
__global__ void __launch_bounds__(256) k_reduce(const float* __restrict__ nll,
                                                const float* __restrict__ msk,
                                                float* __restrict__ out){
  __shared__ float sn[256], sm[256];
  int tid = threadIdx.x;
  float a = 0.f, c = 0.f;
  for (int i = tid; i < NTOK; i += 256){ a += nll[i]; c += msk[i]; }
  sn[tid] = a; sm[tid] = c;
  __syncthreads();
  for (int o = 128; o; o >>= 1){
    if (tid < o){ sn[tid] += sn[tid+o]; sm[tid] += sm[tid+o]; }
    __syncthreads();
  }
  if (tid == 0) out[0] = sn[0] / sm[0];
}

// ---------------- host orchestration (capture-time only) ----------------
extern "C" void kernel_launch(void* const* d_in, const int* in_sizes, int n_in,
                              void* d_out, int out_size){
  (void)in_sizes; (void)n_in; (void)out_size;
  const float* enc   = (const float*)d_in[0];
  const int*   seq   = (const int*)  d_in[1];
  const float* emb   = (const float*)d_in[3];
  const float* inis  = (const float*)d_in[4];
  const float* aWw   = (const float*)d_in[5];
  const float* aWb   = (const float*)d_in[6];
  const float* aUw   = (const float*)d_in[7];
  const float* aUb   = (const float*)d_in[8];
  const float* avw   = (const float*)d_in[9];
  const float* avb   = (const float*)d_in[10];
  const float* fcw   = (const float*)d_in[11];
  const float* fcb   = (const float*)d_in[12];
  const float* clsw  = (const float*)d_in[13];
  const float* clsb  = (const float*)d_in[14];
  const float* g0wih = (const float*)d_in[15];
  const float* g0whh = (const float*)d_in[16];
  const float* g0bih = (const float*)d_in[17];
  const float* g0bhh = (const float*)d_in[18];
  const float* g1wih = (const float*)d_in[19];
  const float* g1whh = (const float*)d_in[20];
  const float* g1bih = (const float*)d_in[21];
  const float* g1bhh = (const float*)d_in[22];

  __nv_bfloat16 *Wsh, *ench, *waWw, *waUw, *wfcw, *w0ih, *w0hh, *w1ih, *w1hh;
  float *xg, *xs, *ys, *y0, *h0b, *h1b, *gp0, *gp1, *fp, *Up, *ctx, *lg, *nll, *msk;
  cudaGetSymbolAddress((void**)&Wsh,  g_Wsh);
  cudaGetSymbolAddress((void**)&ench, g_ench);
  cudaGetSymbolAddress((void**)&waWw, g_w_aWw);
  cudaGetSymbolAddress((void**)&waUw, g_w_aUw);
  cudaGetSymbolAddress((void**)&wfcw, g_w_fcw);
  cudaGetSymbolAddress((void**)&w0ih, g_w_g0wih);
  cudaGetSymbolAddress((void**)&w0hh, g_w_g0whh);
  cudaGetSymbolAddress((void**)&w1ih, g_w_g1wih);
  cudaGetSymbolAddress((void**)&w1hh, g_w_g1whh);
  cudaGetSymbolAddress((void**)&xg,   g_xg);
  cudaGetSymbolAddress((void**)&xs,   g_xs);
  cudaGetSymbolAddress((void**)&ys,   g_ys);
  cudaGetSymbolAddress((void**)&y0,   g_y0);
  cudaGetSymbolAddress((void**)&h0b,  g_h0buf);
  cudaGetSymbolAddress((void**)&h1b,  g_h1buf);
  cudaGetSymbolAddress((void**)&gp0,  g_gp0);
  cudaGetSymbolAddress((void**)&gp1,  g_gp1);
  cudaGetSymbolAddress((void**)&fp,   g_fp);
  cudaGetSymbolAddress((void**)&Up,   g_Up);
  cudaGetSymbolAddress((void**)&ctx,  g_ctx);
  cudaGetSymbolAddress((void**)&lg,   g_lg);
  cudaGetSymbolAddress((void**)&nll,  g_nll);
  cudaGetSymbolAddress((void**)&msk,  g_msk);

  const size_t GSZ = (size_t)BB*3*HH;
  float* GP0[4] = {gp0, gp0+GSZ, gp0+2*GSZ, gp0+3*GSZ};
  float* GP1[4] = {gp1, gp1+GSZ, gp1+2*GSZ, gp1+3*GSZ};
  float* FP[4] = {fp, fp+BH, fp+2*BH, fp+3*BH};
  float* UP[2] = {Up, Up+BH};
  float* LG[2] = {lg, lg+(size_t)NTOK*VV};

  // stream/events created ONCE (first call = correctness run, pre-baseline).
  // Reused on the capture call; no allocations during or after capture.
  static cudaStream_t sB = nullptr;
  static cudaEvent_t evFork, ev0h, ev1h, evpw0, evpw1, evfch;
  if (!sB){
    cudaStreamCreateWithFlags(&sB, cudaStreamNonBlocking);
    cudaEventCreateWithFlags(&evFork, cudaEventDisableTiming);
    cudaEventCreateWithFlags(&ev0h,  cudaEventDisableTiming);
    cudaEventCreateWithFlags(&ev1h,  cudaEventDisableTiming);
    cudaEventCreateWithFlags(&evpw0, cudaEventDisableTiming);
    cudaEventCreateWithFlags(&evpw1, cudaEventDisableTiming);
    cudaEventCreateWithFlags(&evfch, cudaEventDisableTiming);
  }

  // one-time precompute (main stream)
  k_inith<<<(BH+255)/256, 256>>>(inis, h0b, h1b);
  k_embed<<<(TT*BH+255)/256, 256>>>(emb, seq, xs);
  k_tobf16<<<(BB*CC*NL/4+255)/256, 256>>>(enc, ench, BB*CC*NL/4);
  k_tobf16<<<(HH*CC/4+255)/256, 256>>>(aWw, waWw, HH*CC/4);
  k_tobf16<<<(HH*HH/4+255)/256, 256>>>(aUw, waUw, HH*HH/4);
  k_tobf16<<<(HH*(CC+HH)/4+255)/256, 256>>>(fcw, wfcw, HH*(CC+HH)/4);
  k_tobf16<<<(3*HH*2*HH/4+255)/256, 256>>>(g0wih, w0ih, 3*HH*2*HH/4);
  k_tobf16<<<(3*HH*HH/4+255)/256, 256>>>(g0whh, w0hh, 3*HH*HH/4);
  k_tobf16<<<(3*HH*HH/4+255)/256, 256>>>(g1wih, w1ih, 3*HH*HH/4);
  k_tobf16<<<(3*HH*HH/4+255)/256, 256>>>(g1whh, w1hh, 3*HH*HH/4);
  k_wsT<<<dim3(512, 4), 256>>>(ench, waWw, aWb, Wsh);
  k_mmT<<<dim3(92, 12, 1), 256>>>(xs, 512, w0ih, 1024, 512,
                                  xs, 512, w0ih, 1024, 512,
                                  1, 512, xg, 3*HH);

  // y0 (main only)
  {
    k_mmT<<<dim3(4, 4, 2), 256>>>(h1b, HH, waUw, 512, 0,
                                  h1b, HH, waUw, 512, 0,
                                  2, 256, Up, HH);
    k_attn<<<BB, 256>>>(Wsh, ench, UP[0], UP[1], aUb, avw, avb, ctx);
    k_mmT<<<dim3(4, 4, 4), 256>>>(ctx, CC, wfcw, 1024, 0,
                                  h1b, HH, wfcw, 1024, 512,
                                  2, 256, fp, HH);
    k_pwfc<<<BH/256, 256>>>(FP[0], FP[1], FP[2], FP[3], fcb, y0);
  }

  // fork sB: h-recurrent gate halves for t=0
  cudaEventRecord(evFork, 0);
  cudaStreamWaitEvent(sB, evFork, 0);
  k_mmT<<<dim3(4, 12, 2), 256, 0, sB>>>(h0b, HH, w0hh, 512, 0,
                                        h0b, HH, w0hh, 512, 0,
                                        2, 256, GP0[2], 3*HH);
  cudaEventRecord(ev0h, sB);
  k_mmT<<<dim3(4, 12, 2), 256, 0, sB>>>(h1b, HH, w1hh, 512, 0,
                                        h1b, HH, w1hh, 512, 0,
                                        2, 256, GP1[2], 3*HH);
  cudaEventRecord(ev1h, sB);

  const float* yprev = y0;
  for (int t = 0; t < TT; t++){
    float* h0r = h0b + (size_t)(t & 1)*BH;
    float* h0w = h0b + (size_t)((t+1) & 1)*BH;
    float* h1r = h1b + (size_t)(t & 1)*BH;
    float* h1w = h1b + (size_t)((t+1) & 1)*BH;

    // GRU0 input half (critical path)
    k_mmT<<<dim3(4, 12, 2), 256>>>(yprev, HH, w0ih, 1024, 0,
                                   yprev, HH, w0ih, 1024, 0,
                                   2, 256, GP0[0], 3*HH);
    cudaStreamWaitEvent(0, ev0h, 0);
    k_pw<<<BH/256, 256>>>(GP0[0], GP0[1], GP0[2], GP0[3],
                          xg + (size_t)t*GSZ, h0r, g0bih, g0bhh, h0w);
    if (t+1 < TT){
      cudaEventRecord(evpw0, 0);
      cudaStreamWaitEvent(sB, evpw0, 0);
      k_mmT<<<dim3(4, 12, 2), 256, 0, sB>>>(h0w, HH, w0hh, 512, 0,
                                            h0w, HH, w0hh, 512, 0,
                                            2, 256, GP0[2], 3*HH);
      cudaEventRecord(ev0h, sB);
    }

    // GRU1 input half
    k_mmT<<<dim3(4, 12, 2), 256>>>(h0w, HH, w1ih, 512, 0,
                                   h0w, HH, w1ih, 512, 0,
                                   2, 256, GP1[0], 3*HH);
    cudaStreamWaitEvent(0, ev1h, 0);
    k_pw<<<BH/256, 256>>>(GP1[0], GP1[1], GP1[2], GP1[3],
                          (const float*)nullptr, h1r, g1bih, g1bhh, h1w);
    // fork after pw1: next-step h1 gate GEMM AND this step's fc h-half
    cudaEventRecord(evpw1, 0);
    cudaStreamWaitEvent(sB, evpw1, 0);
    if (t+1 < TT){
      k_mmT<<<dim3(4, 12, 2), 256, 0, sB>>>(h1w, HH, w1hh, 512, 0,
                                            h1w, HH, w1hh, 512, 0,
                                            2, 256, GP1[2], 3*HH);
      cudaEventRecord(ev1h, sB);
    }
    k_mmT<<<dim3(4, 4, 2), 256, 0, sB>>>(h1w, HH, wfcw, 1024, 512,
                                         h1w, HH, wfcw, 1024, 512,
                                         2, 256, fp + 2*BH, HH);
    cudaEventRecord(evfch, sB);

    // attention chain (main): Uh, attn, fc ctx-half, pwfc
    k_mmT<<<dim3(4, 4, 2), 256>>>(h1w, HH, waUw, 512, 0,
                                  h1w, HH, waUw, 512, 0,
                                  2, 256, Up, HH);
    k_attn<<<BB, 256>>>(Wsh, ench, UP[0], UP[1], aUb, avw, avb, ctx);
    k_mmT<<<dim3(4, 4, 2), 256>>>(ctx, CC, wfcw, 1024, 0,
                                  ctx, CC, wfcw, 1024, 0,
                                  2, 256, fp, HH);
    cudaStreamWaitEvent(0, evfch, 0);
    k_pwfc<<<BH/256, 256>>>(FP[0], FP[1], FP[2], FP[3], fcb,
                            ys + (size_t)t*BH);
    yprev = ys + (size_t)t*BH;
  }

  // logits + NLL + reduce (main)
  k_g64<<<dim3(92, 1, 2), 256>>>(ys, HH, clsw, 512, 0, LG[0], LG[1], VV);
  k_nll<<<NTOK/256, 256>>>(LG[0], LG[1], clsb, seq, nll, msk);
  k_reduce<<<1, 256>>>(nll, msk, (float*)d_out);
}

// round 15
// speedup vs baseline: 1.1230x; 1.1230x over previous
#include <cuda_runtime.h>
#include <cuda_bf16.h>
#include <cuda_fp8.h>
#include <math.h>

#define BB 256
#define HH 512
#define CC 512
#define NL 128
#define TT 23
#define LSEQ 24
#define VV 64
#define BH (BB*HH)
#define NTOK (TT*BB)
#define KC 32
#define ASTR 40

typedef unsigned long long u64;
typedef unsigned int u32;

__device__ __forceinline__ void MMA16816(float &d0, float &d1, float &d2, float &d3,
                                         u32 a0, u32 a1, u32 a2, u32 a3,
                                         u32 b0, u32 b1){
  asm volatile("mma.sync.aligned.m16n8k16.row.col.f32.bf16.bf16.f32 "
               "{%0,%1,%2,%3},{%4,%5,%6,%7},{%8,%9},{%0,%1,%2,%3};"
               : "+f"(d0), "+f"(d1), "+f"(d2), "+f"(d3)
               : "r"(a0), "r"(a1), "r"(a2), "r"(a3), "r"(b0), "r"(b1));
}
__device__ __forceinline__ u32 BF2U(__nv_bfloat162 v){ return *reinterpret_cast<u32*>(&v); }
__device__ __forceinline__ void FMA2(u64 &d, u64 a, u64 b){
  asm("fma.rn.f32x2 %0, %1, %2, %0;" : "+l"(d) : "l"(a), "l"(b));
}
__device__ __forceinline__ u64 PACK2(float x, float y){
  u64 r; asm("mov.b64 %0, {%1, %2};" : "=l"(r) : "f"(x), "f"(y)); return r;
}
__device__ __forceinline__ float2 UNPK(u64 v){
  float2 r; asm("mov.b64 {%0, %1}, %2;" : "=f"(r.x), "=f"(r.y) : "l"(v)); return r;
}
__device__ __forceinline__ float2 F8X2(unsigned short v){
  __half2_raw h = __nv_cvt_fp8x2_to_halfraw2(v, __NV_E4M3);
  return __half22float2(*(__half2*)&h);
}

// ---------------- static scratch ----------------
__device__ __nv_bfloat16 g_Wsh[(size_t)BB*NL*HH];
__device__ __nv_bfloat16 g_ench[(size_t)BB*CC*NL];
__device__ __nv_fp8_storage_t g_enf8[(size_t)BB*CC*NL];
__device__ __nv_bfloat16 g_w_aWw[HH*CC];
__device__ __nv_bfloat16 g_w_aUw[HH*HH];
__device__ __nv_bfloat16 g_w_fcw[HH*(CC+HH)];
__device__ __nv_bfloat16 g_w_g0wih[3*HH*2*HH];
__device__ __nv_bfloat16 g_w_g0whh[3*HH*HH];
__device__ __nv_bfloat16 g_w_g1wih[3*HH*HH];
__device__ __nv_bfloat16 g_w_g1whh[3*HH*HH];
__device__ float g_xg[(size_t)TT*BB*3*HH];
__device__ float g_xs[(size_t)TT*BH];
__device__ float g_ys[(size_t)TT*BH];
__device__ float g_y0[BH];
__device__ float g_h0buf[2][BH];
__device__ float g_h1buf[2][BH];
__device__ float g_gp0[4][(size_t)BB*3*HH];
__device__ float g_gp1[4][(size_t)BB*3*HH];
__device__ float g_fp[4][BH];
__device__ float g_Up[2][BH];
__device__ float g_ctx[BH];
__device__ float g_lg[2][(size_t)NTOK*VV];
__device__ float g_nll[NTOK];
__device__ float g_msk[NTOK];

// ---------------- init / embed / convert ----------------
__global__ void k_inith(const float* __restrict__ init_state,
                        float* __restrict__ h0, float* __restrict__ h1){
  int idx = blockIdx.x*blockDim.x + threadIdx.x;
  if (idx < BH){
    int j = idx & (HH-1);
    h0[idx] = init_state[j];
    h1[idx] = init_state[HH + j];
  }
}

__global__ void k_embed(const float* __restrict__ emb, const int* __restrict__ seq,
                        float* __restrict__ xs){
  int idx = blockIdx.x*blockDim.x + threadIdx.x;
  if (idx < TT*BH){
    int h = idx & (HH-1);
    int r = idx >> 9;
    int b = r & (BB-1);
    int t = r >> 8;
    int tok = seq[b*LSEQ + t];
    xs[idx] = emb[(size_t)tok*HH + h];
  }
}

__global__ void k_tobf16(const float* __restrict__ in, __nv_bfloat16* __restrict__ out, int n4){
  int idx = blockIdx.x*blockDim.x + threadIdx.x;
  if (idx < n4){
    float4 v = *(const float4*)&in[(size_t)idx*4];
    *(__nv_bfloat162*)&out[(size_t)idx*4]   = __floats2bfloat162_rn(v.x, v.y);
    *(__nv_bfloat162*)&out[(size_t)idx*4+2] = __floats2bfloat162_rn(v.z, v.w);
  }
}

__global__ void k_tofp8(const float* __restrict__ in, __nv_fp8_storage_t* __restrict__ out, int n4){
  int idx = blockIdx.x*blockDim.x + threadIdx.x;
  if (idx < n4){
    float4 v = *(const float4*)&in[(size_t)idx*4];
    u32 lo = __nv_cvt_float2_to_fp8x2(make_float2(v.x, v.y), __NV_SATFINITE, __NV_E4M3);
    u32 hi = __nv_cvt_float2_to_fp8x2(make_float2(v.z, v.w), __NV_SATFINITE, __NV_E4M3);
    *(u32*)&out[(size_t)idx*4] = lo | (hi << 16);
  }
}

// ============ 64x128 mma frag pattern (8 warps of 32x32) ============
#define MMA_FRAGS(AtP, WtP)                                                    \
  _Pragma("unroll")                                                            \
  for (int k16 = 0; k16 < KC; k16 += 16){                                      \
    u32 af[2][4]; u32 bfv[4][2];                                               \
    _Pragma("unroll")                                                          \
    for (int mt = 0; mt < 2; mt++){                                            \
      int r = wm + mt*16 + gid;                                                \
      af[mt][0] = *(const u32*)&(AtP)[r*ASTR      + k16 + tig*2];              \
      af[mt][1] = *(const u32*)&(AtP)[(r+8)*ASTR  + k16 + tig*2];              \
      af[mt][2] = *(const u32*)&(AtP)[r*ASTR      + k16 + tig*2 + 8];          \
      af[mt][3] = *(const u32*)&(AtP)[(r+8)*ASTR  + k16 + tig*2 + 8];          \
    }                                                                          \
    _Pragma("unroll")                                                          \
    for (int nt = 0; nt < 4; nt++){                                            \
      int r = wn + nt*8 + gid;                                                 \
      bfv[nt][0] = *(const u32*)&(WtP)[r*ASTR + k16 + tig*2];                  \
      bfv[nt][1] = *(const u32*)&(WtP)[r*ASTR + k16 + tig*2 + 8];              \
    }                                                                          \
    _Pragma("unroll")                                                          \
    for (int mt = 0; mt < 2; mt++)                                             \
      _Pragma("unroll")                                                        \
      for (int nt = 0; nt < 4; nt++)                                           \
        MMA16816(acc[mt][nt][0], acc[mt][nt][1], acc[mt][nt][2], acc[mt][nt][3],\
                 af[mt][0], af[mt][1], af[mt][2], af[mt][3],                   \
                 bfv[nt][0], bfv[nt][1]);                                      \
  }

// ---------------- generic mma GEMM (2 sets, K-sliced partials) ----------------
__global__ void __launch_bounds__(256) k_mmT(
    const float* __restrict__ A0, int wA0,
    const __nv_bfloat16* __restrict__ W0, int s0, int o0,
    const float* __restrict__ A1, int wA1,
    const __nv_bfloat16* __restrict__ W1, int s1, int o1,
    int zPerSet, int kSlice, float* __restrict__ Cb, int ldc){
  __shared__ __align__(16) __nv_bfloat16 At[2][64*ASTR];
  __shared__ __align__(16) __nv_bfloat16 Wt[2][128*ASTR];
  int z = blockIdx.z;
  int set = z / zPerSet;
  int kb = (z - set*zPerSet) * kSlice;
  const float* A = set ? A1 : A0;
  const __nv_bfloat16* W = set ? W1 : W0;
  int wA = set ? wA1 : wA0;
  int s  = set ? s1 : s0;
  int o  = set ? o1 : o0;
  int M = gridDim.x * 64;
  float* C = Cb + (size_t)z * M * ldc;

  int m0 = blockIdx.x*64, n0 = blockIdx.y*128;
  int tid = threadIdx.x;
  int warp = tid >> 5, lane = tid & 31;
  int wm = (warp & 1)*32, wn = (warp >> 1)*32;
  int gid = lane >> 2, tig = lane & 3;
  float acc[2][4][4] = {};

  float4 ra[2]; uint4 rw[2];
  auto loadT = [&](int t){
    int kc = kb + t*KC;
    #pragma unroll
    for (int i=0;i<2;i++){
      int idx = tid + i*256;
      int r = idx >> 3, k4 = (idx & 7)*4;
      ra[i] = *(const float4*)&A[(size_t)(m0+r)*wA + kc + k4];
      int rr = idx >> 2, k8 = (idx & 3)*8;
      rw[i] = *(const uint4*)&W[(size_t)(n0+rr)*s + o + kc + k8];
    }
  };
  auto storeT = [&](int buf){
    #pragma unroll
    for (int i=0;i<2;i++){
      int idx = tid + i*256;
      int r = idx >> 3, k4 = (idx & 7)*4;
      u32 p0 = BF2U(__floats2bfloat162_rn(ra[i].x, ra[i].y));
      u32 p1 = BF2U(__floats2bfloat162_rn(ra[i].z, ra[i].w));
      *(uint2*)&At[buf][r*ASTR + k4] = make_uint2(p0, p1);
      int rr = idx >> 2, k8 = (idx & 3)*8;
      *(uint4*)&Wt[buf][rr*ASTR + k8] = rw[i];
    }
  };

  int ntc = kSlice / KC;
  loadT(0); storeT(0); __syncthreads();
  for (int t=0;t<ntc;t++){
    int buf = t & 1;
    if (t+1 < ntc) loadT(t+1);
    MMA_FRAGS(At[buf], Wt[buf])
    if (t+1 < ntc) storeT((t+1)&1);
    __syncthreads();
  }

  #pragma unroll
  for (int mt=0;mt<2;mt++){
    #pragma unroll
    for (int nt=0;nt<4;nt++){
      int m = m0 + wm + mt*16 + gid;
      int n = n0 + wn + nt*8 + tig*2;
      *(float2*)&C[(size_t)m*ldc + n]     = make_float2(acc[mt][nt][0], acc[mt][nt][1]);
      *(float2*)&C[(size_t)(m+8)*ldc + n] = make_float2(acc[mt][nt][2], acc[mt][nt][3]);
    }
  }
}

// ---------------- Ws GEMM (bf16 ench A, bf16 out) ----------------
__global__ void __launch_bounds__(256) k_wsT(
    const __nv_bfloat16* __restrict__ ench,
    const __nv_bfloat16* __restrict__ Wwb,
    const float* __restrict__ Wb,
    __nv_bfloat16* __restrict__ Wsh){
  __shared__ __align__(16) __nv_bfloat16 At2[2][64*ASTR];
  __shared__ __align__(16) __nv_bfloat16 Wt2[2][128*ASTR];
  int m0 = blockIdx.x*64;
  int b = m0 >> 7, l0 = m0 & 127;
  int n0 = blockIdx.y*128;
  int tid = threadIdx.x;
  int warp = tid >> 5, lane = tid & 31;
  int wm = (warp & 1)*32, wn = (warp >> 1)*32;
  int gid = lane >> 2, tig = lane & 3;
  float acc[2][4][4] = {};

  uint4 raw; uint4 rw[2];
  int ak = tid >> 3, al8 = (tid & 7)*8;

  auto loadT = [&](int t){
    int kc = t*KC;
    raw = *(const uint4*)&ench[(size_t)b*CC*NL + (size_t)(kc+ak)*NL + l0 + al8];
    #pragma unroll
    for (int i=0;i<2;i++){
      int idx = tid + i*256;
      int rr = idx >> 2, k8 = (idx & 3)*8;
      rw[i] = *(const uint4*)&Wwb[(size_t)(n0+rr)*CC + kc + k8];
    }
  };
  auto storeT = [&](int buf){
    const __nv_bfloat16* src = (const __nv_bfloat16*)&raw;
    #pragma unroll
    for (int i=0;i<8;i++) At2[buf][(al8+i)*ASTR + ak] = src[i];
    #pragma unroll
    for (int i=0;i<2;i++){
      int idx = tid + i*256;
      int rr = idx >> 2, k8 = (idx & 3)*8;
      *(uint4*)&Wt2[buf][rr*ASTR + k8] = rw[i];
    }
  };

  loadT(0); storeT(0); __syncthreads();
  for (int t=0;t<16;t++){
    int buf = t & 1;
    if (t+1 < 16) loadT(t+1);
    MMA_FRAGS(At2[buf], Wt2[buf])
    if (t+1 < 16) storeT((t+1)&1);
    __syncthreads();
  }

  #pragma unroll
  for (int mt=0;mt<2;mt++){
    #pragma unroll
    for (int nt=0;nt<4;nt++){
      int m = m0 + wm + mt*16 + gid;
      int n = n0 + wn + nt*8 + tig*2;
      float2 bi = *(const float2*)&Wb[n];
      *(__nv_bfloat162*)&Wsh[(size_t)m*HH + n] =
          __floats2bfloat162_rn(acc[mt][nt][0]+bi.x, acc[mt][nt][1]+bi.y);
      *(__nv_bfloat162*)&Wsh[(size_t)(m+8)*HH + n] =
          __floats2bfloat162_rn(acc[mt][nt][2]+bi.x, acc[mt][nt][3]+bi.y);
    }
  }
}

// ---------------- logits GEMM (fp32, N=64, K-split 2) ----------------
__global__ void __launch_bounds__(256) k_g64(const float* __restrict__ A0, int wA0,
                                             const float* __restrict__ W0, int s0, int o0,
                                             float* __restrict__ C0, float* __restrict__ C1,
                                             int ldc){
  __shared__ __align__(16) float At[2][16][68];
  __shared__ __align__(16) float Wt[2][16][68];
  int z = blockIdx.z;
  int kbase = z*256;
  float* C = z ? C1 : C0;
  int m0 = blockIdx.x*64, n0 = blockIdx.y*64;
  int tid = threadIdx.x, tm = tid & 15, tn = tid >> 4;
  u64 acc[4][2] = {};
  float4 ra, rw;
  int mm = tid >> 2, k4 = (tid & 3)*4;

  auto loadT = [&](int t){
    int kc = kbase + t*16;
    ra = *(const float4*)&A0[(size_t)(m0+mm)*wA0 + kc + k4];
    rw = *(const float4*)&W0[(size_t)(n0+mm)*s0 + o0 + kc + k4];
  };
  auto storeT = [&](int buf){
    At[buf][k4+0][mm]=ra.x; At[buf][k4+1][mm]=ra.y; At[buf][k4+2][mm]=ra.z; At[buf][k4+3][mm]=ra.w;
    Wt[buf][k4+0][mm]=rw.x; Wt[buf][k4+1][mm]=rw.y; Wt[buf][k4+2][mm]=rw.z; Wt[buf][k4+3][mm]=rw.w;
  };

  loadT(0); storeT(0); __syncthreads();
  for (int t=0;t<16;t++){
    int buf = t & 1;
    if (t+1 < 16) loadT(t+1);
    #pragma unroll
    for (int kk=0;kk<16;kk++){
      float4 av = *(const float4*)&At[buf][kk][tm*4];
      ulonglong2 wv = *(const ulonglong2*)&Wt[buf][kk][tn*4];
      u64 a0=PACK2(av.x,av.x), a1=PACK2(av.y,av.y), a2=PACK2(av.z,av.z), a3=PACK2(av.w,av.w);
      FMA2(acc[0][0],a0,wv.x); FMA2(acc[0][1],a0,wv.y);
      FMA2(acc[1][0],a1,wv.x); FMA2(acc[1][1],a1,wv.y);
      FMA2(acc[2][0],a2,wv.x); FMA2(acc[2][1],a2,wv.y);
      FMA2(acc[3][0],a3,wv.x); FMA2(acc[3][1],a3,wv.y);
    }
    if (t+1 < 16) storeT((t+1)&1);
    __syncthreads();
  }
  #pragma unroll
  for (int mi=0;mi<4;mi++){
    int m = m0 + tm*4 + mi;
    #pragma unroll
    for (int h=0;h<2;h++){
      float2 p = UNPK(acc[mi][h]);
      int n = n0 + tn*4 + h*2;
      *(float2*)&C[(size_t)m*ldc + n] = make_float2(p.x, p.y);
    }
  }
}

// ---------------- GRU pointwise: combine 4 gate partials ----------------
__global__ void __launch_bounds__(256) k_pw(const float* __restrict__ P0,
                                            const float* __restrict__ P1,
                                            const float* __restrict__ P2,
                                            const float* __restrict__ P3,
                                            const float* __restrict__ xg,
                                            const float* __restrict__ hprev,
                                            const float* __restrict__ bih,
                                            const float* __restrict__ bhh,
                                            float* __restrict__ hnew){
  int idx = blockIdx.x*256 + threadIdx.x;
  int b = idx >> 9, j = idx & (HH-1);
  size_t r0 = (size_t)b*(3*HH);
  float gr = P0[r0+j] + P1[r0+j] + P2[r0+j] + P3[r0+j] + bih[j] + bhh[j];
  float gz = P0[r0+HH+j] + P1[r0+HH+j] + P2[r0+HH+j] + P3[r0+HH+j] + bih[HH+j] + bhh[HH+j];
  float gi = P0[r0+2*HH+j] + P1[r0+2*HH+j] + bih[2*HH+j];
  float gh = P2[r0+2*HH+j] + P3[r0+2*HH+j] + bhh[2*HH+j];
  if (xg){
    gr += xg[r0+j]; gz += xg[r0+HH+j]; gi += xg[r0+2*HH+j];
  }
  float r = 1.f/(1.f+expf(-gr));
  float z = 1.f/(1.f+expf(-gz));
  float n = tanhf(gi + r*gh);
  hnew[idx] = (1.f-z)*n + z*hprev[idx];
}

// ---------------- fc pointwise ----------------
__global__ void __launch_bounds__(256) k_pwfc(const float* __restrict__ F0,
                                              const float* __restrict__ F1,
                                              const float* __restrict__ F2,
                                              const float* __restrict__ F3,
                                              const float* __restrict__ fcb,
                                              float* __restrict__ y){
  int idx = blockIdx.x*256 + threadIdx.x;
  int j = idx & (HH-1);
  float v = F0[idx] + F1[idx] + F2[idx] + F3[idx] + fcb[j];
  y[idx] = fmaxf(v, 0.f);
}

// ---------------- attention: scores on bf16 Ws, ctx on fp8 enc ----------------
__global__ void __launch_bounds__(256) k_attn(const __nv_bfloat16* __restrict__ Wsh,
                                              const __nv_fp8_storage_t* __restrict__ enf8,
                                              const float* __restrict__ UhA,
                                              const float* __restrict__ UhB,
                                              const float* __restrict__ aUb,
                                              const float* __restrict__ vw,
                                              const float* __restrict__ vb,
                                              float* __restrict__ ctx){
  __shared__ __align__(16) float us[HH];
  __shared__ __align__(16) float vs[HH];
  __shared__ __align__(16) float sc[NL];
  int b = blockIdx.x, tid = threadIdx.x;

  {
    float2 a = *(const float2*)&UhA[(size_t)b*HH + tid*2];
    float2 c = *(const float2*)&UhB[(size_t)b*HH + tid*2];
    float2 u = *(const float2*)&aUb[tid*2];
    us[tid*2]   = a.x + c.x + u.x;
    us[tid*2+1] = a.y + c.y + u.y;
    *(float2*)&vs[tid*2] = *(const float2*)&vw[tid*2];
  }
  __syncthreads();

  {
    int l = tid >> 1, half = tid & 1;
    const uint4* wp = (const uint4*)(Wsh + ((size_t)(b*NL + l))*HH + half*256);
    float s = 0.f;
    #pragma unroll 4
    for (int i=0;i<32;i++){
      uint4 q = wp[i];
      const __nv_bfloat162* h2 = (const __nv_bfloat162*)&q;
      int off = half*256 + i*8;
      float4 u0 = *(const float4*)&us[off];
      float4 u1 = *(const float4*)&us[off+4];
      float4 v0 = *(const float4*)&vs[off];
      float4 v1 = *(const float4*)&vs[off+4];
      float2 w0=__bfloat1622float2(h2[0]), w1=__bfloat1622float2(h2[1]);
      float2 w2=__bfloat1622float2(h2[2]), w3=__bfloat1622float2(h2[3]);
      s += fmaxf(w0.x+u0.x,0.f)*v0.x + fmaxf(w0.y+u0.y,0.f)*v0.y
         + fmaxf(w1.x+u0.z,0.f)*v0.z + fmaxf(w1.y+u0.w,0.f)*v0.w
         + fmaxf(w2.x+u1.x,0.f)*v1.x + fmaxf(w2.y+u1.y,0.f)*v1.y
         + fmaxf(w3.x+u1.z,0.f)*v1.z + fmaxf(w3.y+u1.w,0.f)*v1.w;
    }
    s += __shfl_xor_sync(0xffffffffu, s, 1);
    if (!half) sc[l] = s + vb[0];
  }
  __syncthreads();
  if (tid < 32){
    float m = -1e30f;
    for (int l = tid; l < NL; l += 32) m = fmaxf(m, sc[l]);
    #pragma unroll
    for (int o=16;o;o>>=1) m = fmaxf(m, __shfl_xor_sync(0xffffffffu,m,o));
    float s = 0.f;
    for (int l = tid; l < NL; l += 32){ float e = expf(sc[l]-m); sc[l] = e; s += e; }
    #pragma unroll
    for (int o=16;o;o>>=1) s += __shfl_xor_sync(0xffffffffu,s,o);
    float inv = 1.f/s;
    for (int l = tid; l < NL; l += 32) sc[l] *= inv;
  }
  __syncthreads();
  // ctx: fp8 enc rows (128 B per channel)
  #pragma unroll
  for (int cc=0;cc<2;cc++){
    int c = tid + cc*256;
    const uint4* ep = (const uint4*)(enf8 + ((size_t)b*CC + c)*NL);
    float s = 0.f;
    #pragma unroll
    for (int i=0;i<8;i++){
      uint4 q = ep[i];
      const unsigned short* p2 = (const unsigned short*)&q;
      #pragma unroll
      for (int j=0;j<8;j++){
        float2 e = F8X2(p2[j]);
        float2 a = *(const float2*)&sc[i*16 + j*2];
        s += e.x*a.x + e.y*a.y;
      }
    }
    ctx[(size_t)b*CC + c] = s;
  }
}

// ---------------- per-token NLL ----------------
__global__ void __launch_bounds__(256) k_nll(const float* __restrict__ LA,
                                             const float* __restrict__ LB,
                                             const float* __restrict__ clsb,
                                             const int* __restrict__ seq,
                                             float* __restrict__ nll,
                                             float* __restrict__ msk){
  int idx = blockIdx.x*256 + threadIdx.x;
  int t = idx >> 8, b = idx & 255;
  float lg[VV];
  const float4* pa = (const float4*)(LA + (size_t)idx*VV);
  const float4* pb = (const float4*)(LB + (size_t)idx*VV);
  float m = -1e30f;
  #pragma unroll
  for (int i=0;i<16;i++){
    float4 a = pa[i], c = pb[i];
    float4 d = *(const float4*)&clsb[i*4];
    lg[i*4+0] = a.x + c.x + d.x;
    lg[i*4+1] = a.y + c.y + d.y;
    lg[i*4+2] = a.z + c.z + d.z;
    lg[i*4+3] = a.w + c.w + d.w;
  }
  #pragma unroll
  for (int v=0;v<VV;v++) m = fmaxf(m, lg[v]);
  float se = 0.f;
  #pragma unroll
  for (int v=0;v<VV;v++) se += expf(lg[v]-m);
  int label = seq[b*LSEQ + t + 1];
  float lp = lg[label] - m - logf(se);
  bool mk = label > 0;
  nll[idx] = mk ? -lp : 0.f;
  msk[idx] = mk ? 1.f : 0.f;
}

// ---------------- deterministic final reduction ----------------
__global__ void __launch_bounds__(256) k_reduce(const float* __restrict__ nll,
                                                const float* __restrict__ msk,
                                                float* __restrict__ out){
  __shared__ float sn[256], sm[256];
  int tid = threadIdx.x;
  float a = 0.f, c = 0.f;
  for (int i = tid; i < NTOK; i += 256){ a += nll[i]; c += msk[i]; }
  sn[tid] = a; sm[tid] = c;
  __syncthreads();
  for (int o = 128; o; o >>= 1){
    if (tid < o){ sn[tid] += sn[tid+o]; sm[tid] += sm[tid+o]; }
    __syncthreads();
  }
  if (tid == 0) out[0] = sn[0] / sm[0];
}

// ---------------- host orchestration (capture-time only) ----------------
extern "C" void kernel_launch(void* const* d_in, const int* in_sizes, int n_in,
                              void* d_out, int out_size){
  (void)in_sizes; (void)n_in; (void)out_size;
  const float* enc   = (const float*)d_in[0];
  const int*   seq   = (const int*)  d_in[1];
  const float* emb   = (const float*)d_in[3];
  const float* inis  = (const float*)d_in[4];
  const float* aWw   = (const float*)d_in[5];
  const float* aWb   = (const float*)d_in[6];
  const float* aUw   = (const float*)d_in[7];
  const float* aUb   = (const float*)d_in[8];
  const float* avw   = (const float*)d_in[9];
  const float* avb   = (const float*)d_in[10];
  const float* fcw   = (const float*)d_in[11];
  const float* fcb   = (const float*)d_in[12];
  const float* clsw  = (const float*)d_in[13];
  const float* clsb  = (const float*)d_in[14];
  const float* g0wih = (const float*)d_in[15];
  const float* g0whh = (const float*)d_in[16];
  const float* g0bih = (const float*)d_in[17];
  const float* g0bhh = (const float*)d_in[18];
  const float* g1wih = (const float*)d_in[19];
  const float* g1whh = (const float*)d_in[20];
  const float* g1bih = (const float*)d_in[21];
  const float* g1bhh = (const float*)d_in[22];

  __nv_bfloat16 *Wsh, *ench, *waWw, *waUw, *wfcw, *w0ih, *w0hh, *w1ih, *w1hh;
  __nv_fp8_storage_t *enf8;
  float *xg, *xs, *ys, *y0, *h0b, *h1b, *gp0, *gp1, *fp, *Up, *ctx, *lg, *nll, *msk;
  cudaGetSymbolAddress((void**)&Wsh,  g_Wsh);
  cudaGetSymbolAddress((void**)&ench, g_ench);
  cudaGetSymbolAddress((void**)&enf8, g_enf8);
  cudaGetSymbolAddress((void**)&waWw, g_w_aWw);
  cudaGetSymbolAddress((void**)&waUw, g_w_aUw);
  cudaGetSymbolAddress((void**)&wfcw, g_w_fcw);
  cudaGetSymbolAddress((void**)&w0ih, g_w_g0wih);
  cudaGetSymbolAddress((void**)&w0hh, g_w_g0whh);
  cudaGetSymbolAddress((void**)&w1ih, g_w_g1wih);
  cudaGetSymbolAddress((void**)&w1hh, g_w_g1whh);
  cudaGetSymbolAddress((void**)&xg,   g_xg);
  cudaGetSymbolAddress((void**)&xs,   g_xs);
  cudaGetSymbolAddress((void**)&ys,   g_ys);
  cudaGetSymbolAddress((void**)&y0,   g_y0);
  cudaGetSymbolAddress((void**)&h0b,  g_h0buf);
  cudaGetSymbolAddress((void**)&h1b,  g_h1buf);
  cudaGetSymbolAddress((void**)&gp0,  g_gp0);
  cudaGetSymbolAddress((void**)&gp1,  g_gp1);
  cudaGetSymbolAddress((void**)&fp,   g_fp);
  cudaGetSymbolAddress((void**)&Up,   g_Up);
  cudaGetSymbolAddress((void**)&ctx,  g_ctx);
  cudaGetSymbolAddress((void**)&lg,   g_lg);
  cudaGetSymbolAddress((void**)&nll,  g_nll);
  cudaGetSymbolAddress((void**)&msk,  g_msk);

  const size_t GSZ = (size_t)BB*3*HH;
  float* GP0[4] = {gp0, gp0+GSZ, gp0+2*GSZ, gp0+3*GSZ};
  float* GP1[4] = {gp1, gp1+GSZ, gp1+2*GSZ, gp1+3*GSZ};
  float* FP[4] = {fp, fp+BH, fp+2*BH, fp+3*BH};
  float* UP[2] = {Up, Up+BH};
  float* LG[2] = {lg, lg+(size_t)NTOK*VV};

  // stream/events created ONCE (first call = correctness run, pre-baseline)
  static cudaStream_t sB = nullptr;
  static cudaEvent_t evFork, ev0h, ev1h, evpw0, evpw1;
  if (!sB){
    cudaStreamCreateWithFlags(&sB, cudaStreamNonBlocking);
    cudaEventCreateWithFlags(&evFork, cudaEventDisableTiming);
    cudaEventCreateWithFlags(&ev0h,  cudaEventDisableTiming);
    cudaEventCreateWithFlags(&ev1h,  cudaEventDisableTiming);
    cudaEventCreateWithFlags(&evpw0, cudaEventDisableTiming);
    cudaEventCreateWithFlags(&evpw1, cudaEventDisableTiming);
  }

  // one-time precompute (main stream)
  k_inith<<<(BH+255)/256, 256>>>(inis, h0b, h1b);
  k_embed<<<(TT*BH+255)/256, 256>>>(emb, seq, xs);
  k_tobf16<<<(BB*CC*NL/4+255)/256, 256>>>(enc, ench, BB*CC*NL/4);
  k_tofp8<<<(BB*CC*NL/4+255)/256, 256>>>(enc, enf8, BB*CC*NL/4);
  k_tobf16<<<(HH*CC/4+255)/256, 256>>>(aWw, waWw, HH*CC/4);
  k_tobf16<<<(HH*HH/4+255)/256, 256>>>(aUw, waUw, HH*HH/4);
  k_tobf16<<<(HH*(CC+HH)/4+255)/256, 256>>>(fcw, wfcw, HH*(CC+HH)/4);
  k_tobf16<<<(3*HH*2*HH/4+255)/256, 256>>>(g0wih, w0ih, 3*HH*2*HH/4);
  k_tobf16<<<(3*HH*HH/4+255)/256, 256>>>(g0whh, w0hh, 3*HH*HH/4);
  k_tobf16<<<(3*HH*HH/4+255)/256, 256>>>(g1wih, w1ih, 3*HH*HH/4);
  k_tobf16<<<(3*HH*HH/4+255)/256, 256>>>(g1whh, w1hh, 3*HH*HH/4);
  k_wsT<<<dim3(512, 4), 256>>>(ench, waWw, aWb, Wsh);
  k_mmT<<<dim3(92, 12, 1), 256>>>(xs, 512, w0ih, 1024, 512,
                                  xs, 512, w0ih, 1024, 512,
                                  1, 512, xg, 3*HH);

  auto attn_fc = [&](const float* h1cur, float* yout){
    k_mmT<<<dim3(4, 4, 2), 256>>>(h1cur, HH, waUw, 512, 0,
                                  h1cur, HH, waUw, 512, 0,
                                  2, 256, Up, HH);
    k_attn<<<BB, 256>>>(Wsh, enf8, UP[0], UP[1], aUb, avw, avb, ctx);
    k_mmT<<<dim3(4, 4, 4), 256>>>(ctx, CC, wfcw, 1024, 0,
                                  h1cur, HH, wfcw, 1024, 512,
                                  2, 256, fp, HH);
    k_pwfc<<<BH/256, 256>>>(FP[0], FP[1], FP[2], FP[3], fcb, yout);
  };

  // y0 on main
  attn_fc(h1b, y0);

  // fork sB: h-recurrent gate halves for t=0
  cudaEventRecord(evFork, 0);
  cudaStreamWaitEvent(sB, evFork, 0);
  k_mmT<<<dim3(4, 12, 2), 256, 0, sB>>>(h0b, HH, w0hh, 512, 0,
                                        h0b, HH, w0hh, 512, 0,
                                        2, 256, GP0[2], 3*HH);
  cudaEventRecord(ev0h, sB);
  k_mmT<<<dim3(4, 12, 2), 256, 0, sB>>>(h1b, HH, w1hh, 512, 0,
                                        h1b, HH, w1hh, 512, 0,
                                        2, 256, GP1[2], 3*HH);
  cudaEventRecord(ev1h, sB);

  const float* yprev = y0;
  for (int t = 0; t < TT; t++){
    float* h0r = h0b + (size_t)(t & 1)*BH;
    float* h0w = h0b + (size_t)((t+1) & 1)*BH;
    float* h1r = h1b + (size_t)(t & 1)*BH;
    float* h1w = h1b + (size_t)((t+1) & 1)*BH;

    // GRU0 input half (critical path)
    k_mmT<<<dim3(4, 12, 2), 256>>>(yprev, HH, w0ih, 1024, 0,
                                   yprev, HH, w0ih, 1024, 0,
                                   2, 256, GP0[0], 3*HH);
    cudaStreamWaitEvent(0, ev0h, 0);
    k_pw<<<BH/256, 256>>>(GP0[0], GP0[1], GP0[2], GP0[3],
                          xg + (size_t)t*GSZ, h0r, g0bih, g0bhh, h0w);
    if (t+1 < TT){
      cudaEventRecord(evpw0, 0);
      cudaStreamWaitEvent(sB, evpw0, 0);
      k_mmT<<<dim3(4, 12, 2), 256, 0, sB>>>(h0w, HH, w0hh, 512, 0,
                                            h0w, HH, w0hh, 512, 0,
                                            2, 256, GP0[2], 3*HH);
      cudaEventRecord(ev0h, sB);
    }

    // GRU1 input half
    k_mmT<<<dim3(4, 12, 2), 256>>>(h0w, HH, w1ih, 512, 0,
                                   h0w, HH, w1ih, 512, 0,
                                   2, 256, GP1[0], 3*HH);
    cudaStreamWaitEvent(0, ev1h, 0);
    k_pw<<<BH/256, 256>>>(GP1[0], GP1[1], GP1[2], GP1[3],
                          (const float*)nullptr, h1r, g1bih, g1bhh, h1w);
    if (t+1 < TT){
      cudaEventRecord(evpw1, 0);
      cudaStreamWaitEvent(sB, evpw1, 0);
      k_mmT<<<dim3(4, 12, 2), 256, 0, sB>>>(h1w, HH, w1hh, 512, 0,
                                            h1w, HH, w1hh, 512, 0,
                                            2, 256, GP1[2], 3*HH);
      cudaEventRecord(ev1h, sB);
    }

    // attention + out_proj (main)
    attn_fc(h1w, ys + (size_t)t*BH);
    yprev = ys + (size_t)t*BH;
  }

  // logits + NLL + reduce (main)
  k_g64<<<dim3(92, 1, 2), 256>>>(ys, HH, clsw, 512, 0, LG[0], LG[1], VV);
  k_nll<<<NTOK/256, 256>>>(LG[0], LG[1], clsb, seq, nll, msk);
  k_reduce<<<1, 256>>>(nll, msk, (float*)d_out);
}

// round 16
// speedup vs baseline: 1.2160x; 1.0829x over previous
#include <cuda_runtime.h>
#include <cuda_bf16.h>
#include <cuda_fp8.h>
#include <math.h>

#define BB 256
#define HH 512
#define CC 512
#define NL 128
#define TT 23
#define LSEQ 24
#define VV 64
#define BH (BB*HH)
#define NTOK (TT*BB)
#define KC 32
#define ASTR 40

typedef unsigned long long u64;
typedef unsigned int u32;

__device__ __forceinline__ void MMA16816(float &d0, float &d1, float &d2, float &d3,
                                         u32 a0, u32 a1, u32 a2, u32 a3,
                                         u32 b0, u32 b1){
  asm volatile("mma.sync.aligned.m16n8k16.row.col.f32.bf16.bf16.f32 "
               "{%0,%1,%2,%3},{%4,%5,%6,%7},{%8,%9},{%0,%1,%2,%3};"
               : "+f"(d0), "+f"(d1), "+f"(d2), "+f"(d3)
               : "r"(a0), "r"(a1), "r"(a2), "r"(a3), "r"(b0), "r"(b1));
}
__device__ __forceinline__ u32 BF2U(__nv_bfloat162 v){ return *reinterpret_cast<u32*>(&v); }
__device__ __forceinline__ void FMA2(u64 &d, u64 a, u64 b){
  asm("fma.rn.f32x2 %0, %1, %2, %0;" : "+l"(d) : "l"(a), "l"(b));
}
__device__ __forceinline__ u64 PACK2(float x, float y){
  u64 r; asm("mov.b64 %0, {%1, %2};" : "=l"(r) : "f"(x), "f"(y)); return r;
}
__device__ __forceinline__ float2 UNPK(u64 v){
  float2 r; asm("mov.b64 {%0, %1}, %2;" : "=f"(r.x), "=f"(r.y) : "l"(v)); return r;
}
__device__ __forceinline__ float2 F8X2(unsigned short v){
  __half2_raw h = __nv_cvt_fp8x2_to_halfraw2(v, __NV_E4M3);
  return __half22float2(*(__half2*)&h);
}

// ---------------- static scratch ----------------
__device__ __nv_fp8_storage_t g_Wsf8[(size_t)BB*NL*HH];
__device__ __nv_bfloat16 g_ench[(size_t)BB*CC*NL];
__device__ __nv_fp8_storage_t g_enf8[(size_t)BB*CC*NL];
__device__ __nv_bfloat16 g_w_aWw[HH*CC];
__device__ __nv_bfloat16 g_w_aUw[HH*HH];
__device__ __nv_bfloat16 g_w_fcw[HH*(CC+HH)];
__device__ __nv_bfloat16 g_w_g0wih[3*HH*2*HH];
__device__ __nv_bfloat16 g_w_g0whh[3*HH*HH];
__device__ __nv_bfloat16 g_w_g1wih[3*HH*HH];
__device__ __nv_bfloat16 g_w_g1whh[3*HH*HH];
__device__ float g_xg[(size_t)TT*BB*3*HH];
__device__ float g_xs[(size_t)TT*BH];
__device__ float g_ys[(size_t)TT*BH];
__device__ float g_y0[BH];
__device__ float g_h0buf[2][BH];
__device__ float g_h1buf[2][BH];
__device__ float g_gp0[4][(size_t)BB*3*HH];
__device__ float g_gp1[4][(size_t)BB*3*HH];
__device__ float g_fp[4][BH];
__device__ float g_Up[2][BH];
__device__ float g_ctx[BH];
__device__ float g_lg[2][(size_t)NTOK*VV];
__device__ float g_nll[NTOK];
__device__ float g_msk[NTOK];

// ---------------- init / embed / convert ----------------
__global__ void k_inith(const float* __restrict__ init_state,
                        float* __restrict__ h0, float* __restrict__ h1){
  int idx = blockIdx.x*blockDim.x + threadIdx.x;
  if (idx < BH){
    int j = idx & (HH-1);
    h0[idx] = init_state[j];
    h1[idx] = init_state[HH + j];
  }
}

__global__ void k_embed(const float* __restrict__ emb, const int* __restrict__ seq,
                        float* __restrict__ xs){
  int idx = blockIdx.x*blockDim.x + threadIdx.x;
  if (idx < TT*BH){
    int h = idx & (HH-1);
    int r = idx >> 9;
    int b = r & (BB-1);
    int t = r >> 8;
    int tok = seq[b*LSEQ + t];
    xs[idx] = emb[(size_t)tok*HH + h];
  }
}

__global__ void k_tobf16(const float* __restrict__ in, __nv_bfloat16* __restrict__ out, int n4){
  int idx = blockIdx.x*blockDim.x + threadIdx.x;
  if (idx < n4){
    float4 v = *(const float4*)&in[(size_t)idx*4];
    *(__nv_bfloat162*)&out[(size_t)idx*4]   = __floats2bfloat162_rn(v.x, v.y);
    *(__nv_bfloat162*)&out[(size_t)idx*4+2] = __floats2bfloat162_rn(v.z, v.w);
  }
}

__global__ void k_tofp8(const float* __restrict__ in, __nv_fp8_storage_t* __restrict__ out, int n4){
  int idx = blockIdx.x*blockDim.x + threadIdx.x;
  if (idx < n4){
    float4 v = *(const float4*)&in[(size_t)idx*4];
    u32 lo = __nv_cvt_float2_to_fp8x2(make_float2(v.x, v.y), __NV_SATFINITE, __NV_E4M3);
    u32 hi = __nv_cvt_float2_to_fp8x2(make_float2(v.z, v.w), __NV_SATFINITE, __NV_E4M3);
    *(u32*)&out[(size_t)idx*4] = lo | (hi << 16);
  }
}

// ============ 64x128 mma frag pattern (8 warps of 32x32) ============
#define MMA_FRAGS(AtP, WtP)                                                    \
  _Pragma("unroll")                                                            \
  for (int k16 = 0; k16 < KC; k16 += 16){                                      \
    u32 af[2][4]; u32 bfv[4][2];                                               \
    _Pragma("unroll")                                                          \
    for (int mt = 0; mt < 2; mt++){                                            \
      int r = wm + mt*16 + gid;                                                \
      af[mt][0] = *(const u32*)&(AtP)[r*ASTR      + k16 + tig*2];              \
      af[mt][1] = *(const u32*)&(AtP)[(r+8)*ASTR  + k16 + tig*2];              \
      af[mt][2] = *(const u32*)&(AtP)[r*ASTR      + k16 + tig*2 + 8];          \
      af[mt][3] = *(const u32*)&(AtP)[(r+8)*ASTR  + k16 + tig*2 + 8];          \
    }                                                                          \
    _Pragma("unroll")                                                          \
    for (int nt = 0; nt < 4; nt++){                                            \
      int r = wn + nt*8 + gid;                                                 \
      bfv[nt][0] = *(const u32*)&(WtP)[r*ASTR + k16 + tig*2];                  \
      bfv[nt][1] = *(const u32*)&(WtP)[r*ASTR + k16 + tig*2 + 8];              \
    }                                                                          \
    _Pragma("unroll")                                                          \
    for (int mt = 0; mt < 2; mt++)                                             \
      _Pragma("unroll")                                                        \
      for (int nt = 0; nt < 4; nt++)                                           \
        MMA16816(acc[mt][nt][0], acc[mt][nt][1], acc[mt][nt][2], acc[mt][nt][3],\
                 af[mt][0], af[mt][1], af[mt][2], af[mt][3],                   \
                 bfv[nt][0], bfv[nt][1]);                                      \
  }

// ---------------- generic mma GEMM (2 sets, K-sliced partials) ----------------
__global__ void __launch_bounds__(256) k_mmT(
    const float* __restrict__ A0, int wA0,
    const __nv_bfloat16* __restrict__ W0, int s0, int o0,
    const float* __restrict__ A1, int wA1,
    const __nv_bfloat16* __restrict__ W1, int s1, int o1,
    int zPerSet, int kSlice, float* __restrict__ Cb, int ldc){
  __shared__ __align__(16) __nv_bfloat16 At[2][64*ASTR];
  __shared__ __align__(16) __nv_bfloat16 Wt[2][128*ASTR];
  int z = blockIdx.z;
  int set = z / zPerSet;
  int kb = (z - set*zPerSet) * kSlice;
  const float* A = set ? A1 : A0;
  const __nv_bfloat16* W = set ? W1 : W0;
  int wA = set ? wA1 : wA0;
  int s  = set ? s1 : s0;
  int o  = set ? o1 : o0;
  int M = gridDim.x * 64;
  float* C = Cb + (size_t)z * M * ldc;

  int m0 = blockIdx.x*64, n0 = blockIdx.y*128;
  int tid = threadIdx.x;
  int warp = tid >> 5, lane = tid & 31;
  int wm = (warp & 1)*32, wn = (warp >> 1)*32;
  int gid = lane >> 2, tig = lane & 3;
  float acc[2][4][4] = {};

  float4 ra[2]; uint4 rw[2];
  auto loadT = [&](int t){
    int kc = kb + t*KC;
    #pragma unroll
    for (int i=0;i<2;i++){
      int idx = tid + i*256;
      int r = idx >> 3, k4 = (idx & 7)*4;
      ra[i] = *(const float4*)&A[(size_t)(m0+r)*wA + kc + k4];
      int rr = idx >> 2, k8 = (idx & 3)*8;
      rw[i] = *(const uint4*)&W[(size_t)(n0+rr)*s + o + kc + k8];
    }
  };
  auto storeT = [&](int buf){
    #pragma unroll
    for (int i=0;i<2;i++){
      int idx = tid + i*256;
      int r = idx >> 3, k4 = (idx & 7)*4;
      u32 p0 = BF2U(__floats2bfloat162_rn(ra[i].x, ra[i].y));
      u32 p1 = BF2U(__floats2bfloat162_rn(ra[i].z, ra[i].w));
      *(uint2*)&At[buf][r*ASTR + k4] = make_uint2(p0, p1);
      int rr = idx >> 2, k8 = (idx & 3)*8;
      *(uint4*)&Wt[buf][rr*ASTR + k8] = rw[i];
    }
  };

  int ntc = kSlice / KC;
  loadT(0); storeT(0); __syncthreads();
  for (int t=0;t<ntc;t++){
    int buf = t & 1;
    if (t+1 < ntc) loadT(t+1);
    MMA_FRAGS(At[buf], Wt[buf])
    if (t+1 < ntc) storeT((t+1)&1);
    __syncthreads();
  }

  #pragma unroll
  for (int mt=0;mt<2;mt++){
    #pragma unroll
    for (int nt=0;nt<4;nt++){
      int m = m0 + wm + mt*16 + gid;
      int n = n0 + wn + nt*8 + tig*2;
      *(float2*)&C[(size_t)m*ldc + n]     = make_float2(acc[mt][nt][0], acc[mt][nt][1]);
      *(float2*)&C[(size_t)(m+8)*ldc + n] = make_float2(acc[mt][nt][2], acc[mt][nt][3]);
    }
  }
}

// ---------------- Ws GEMM (bf16 ench A, fp8 out) ----------------
__global__ void __launch_bounds__(256) k_wsT(
    const __nv_bfloat16* __restrict__ ench,
    const __nv_bfloat16* __restrict__ Wwb,
    const float* __restrict__ Wb,
    __nv_fp8_storage_t* __restrict__ Wsf8){
  __shared__ __align__(16) __nv_bfloat16 At2[2][64*ASTR];
  __shared__ __align__(16) __nv_bfloat16 Wt2[2][128*ASTR];
  int m0 = blockIdx.x*64;
  int b = m0 >> 7, l0 = m0 & 127;
  int n0 = blockIdx.y*128;
  int tid = threadIdx.x;
  int warp = tid >> 5, lane = tid & 31;
  int wm = (warp & 1)*32, wn = (warp >> 1)*32;
  int gid = lane >> 2, tig = lane & 3;
  float acc[2][4][4] = {};

  uint4 raw; uint4 rw[2];
  int ak = tid >> 3, al8 = (tid & 7)*8;

  auto loadT = [&](int t){
    int kc = t*KC;
    raw = *(const uint4*)&ench[(size_t)b*CC*NL + (size_t)(kc+ak)*NL + l0 + al8];
    #pragma unroll
    for (int i=0;i<2;i++){
      int idx = tid + i*256;
      int rr = idx >> 2, k8 = (idx & 3)*8;
      rw[i] = *(const uint4*)&Wwb[(size_t)(n0+rr)*CC + kc + k8];
    }
  };
  auto storeT = [&](int buf){
    const __nv_bfloat16* src = (const __nv_bfloat16*)&raw;
    #pragma unroll
    for (int i=0;i<8;i++) At2[buf][(al8+i)*ASTR + ak] = src[i];
    #pragma unroll
    for (int i=0;i<2;i++){
      int idx = tid + i*256;
      int rr = idx >> 2, k8 = (idx & 3)*8;
      *(uint4*)&Wt2[buf][rr*ASTR + k8] = rw[i];
    }
  };

  loadT(0); storeT(0); __syncthreads();
  for (int t=0;t<16;t++){
    int buf = t & 1;
    if (t+1 < 16) loadT(t+1);
    MMA_FRAGS(At2[buf], Wt2[buf])
    if (t+1 < 16) storeT((t+1)&1);
    __syncthreads();
  }

  #pragma unroll
  for (int mt=0;mt<2;mt++){
    #pragma unroll
    for (int nt=0;nt<4;nt++){
      int m = m0 + wm + mt*16 + gid;
      int n = n0 + wn + nt*8 + tig*2;
      float2 bi = *(const float2*)&Wb[n];
      unsigned short lo = __nv_cvt_float2_to_fp8x2(
          make_float2(acc[mt][nt][0]+bi.x, acc[mt][nt][1]+bi.y),
          __NV_SATFINITE, __NV_E4M3);
      unsigned short hi = __nv_cvt_float2_to_fp8x2(
          make_float2(acc[mt][nt][2]+bi.x, acc[mt][nt][3]+bi.y),
          __NV_SATFINITE, __NV_E4M3);
      *(unsigned short*)&Wsf8[(size_t)m*HH + n]     = lo;
      *(unsigned short*)&Wsf8[(size_t)(m+8)*HH + n] = hi;
    }
  }
}

// ---------------- logits GEMM (fp32, N=64, K-split 2) ----------------
__global__ void __launch_bounds__(256) k_g64(const float* __restrict__ A0, int wA0,
                                             const float* __restrict__ W0, int s0, int o0,
                                             float* __restrict__ C0, float* __restrict__ C1,
                                             int ldc){
  __shared__ __align__(16) float At[2][16][68];
  __shared__ __align__(16) float Wt[2][16][68];
  int z = blockIdx.z;
  int kbase = z*256;
  float* C = z ? C1 : C0;
  int m0 = blockIdx.x*64, n0 = blockIdx.y*64;
  int tid = threadIdx.x, tm = tid & 15, tn = tid >> 4;
  u64 acc[4][2] = {};
  float4 ra, rw;
  int mm = tid >> 2, k4 = (tid & 3)*4;

  auto loadT = [&](int t){
    int kc = kbase + t*16;
    ra = *(const float4*)&A0[(size_t)(m0+mm)*wA0 + kc + k4];
    rw = *(const float4*)&W0[(size_t)(n0+mm)*s0 + o0 + kc + k4];
  };
  auto storeT = [&](int buf){
    At[buf][k4+0][mm]=ra.x; At[buf][k4+1][mm]=ra.y; At[buf][k4+2][mm]=ra.z; At[buf][k4+3][mm]=ra.w;
    Wt[buf][k4+0][mm]=rw.x; Wt[buf][k4+1][mm]=rw.y; Wt[buf][k4+2][mm]=rw.z; Wt[buf][k4+3][mm]=rw.w;
  };

  loadT(0); storeT(0); __syncthreads();
  for (int t=0;t<16;t++){
    int buf = t & 1;
    if (t+1 < 16) loadT(t+1);
    #pragma unroll
    for (int kk=0;kk<16;kk++){
      float4 av = *(const float4*)&At[buf][kk][tm*4];
      ulonglong2 wv = *(const ulonglong2*)&Wt[buf][kk][tn*4];
      u64 a0=PACK2(av.x,av.x), a1=PACK2(av.y,av.y), a2=PACK2(av.z,av.z), a3=PACK2(av.w,av.w);
      FMA2(acc[0][0],a0,wv.x); FMA2(acc[0][1],a0,wv.y);
      FMA2(acc[1][0],a1,wv.x); FMA2(acc[1][1],a1,wv.y);
      FMA2(acc[2][0],a2,wv.x); FMA2(acc[2][1],a2,wv.y);
      FMA2(acc[3][0],a3,wv.x); FMA2(acc[3][1],a3,wv.y);
    }
    if (t+1 < 16) storeT((t+1)&1);
    __syncthreads();
  }
  #pragma unroll
  for (int mi=0;mi<4;mi++){
    int m = m0 + tm*4 + mi;
    #pragma unroll
    for (int h=0;h<2;h++){
      float2 p = UNPK(acc[mi][h]);
      int n = n0 + tn*4 + h*2;
      *(float2*)&C[(size_t)m*ldc + n] = make_float2(p.x, p.y);
    }
  }
}

// ---------------- GRU pointwise: combine 4 gate partials ----------------
__global__ void __launch_bounds__(256) k_pw(const float* __restrict__ P0,
                                            const float* __restrict__ P1,
                                            const float* __restrict__ P2,
                                            const float* __restrict__ P3,
                                            const float* __restrict__ xg,
                                            const float* __restrict__ hprev,
                                            const float* __restrict__ bih,
                                            const float* __restrict__ bhh,
                                            float* __restrict__ hnew){
  int idx = blockIdx.x*256 + threadIdx.x;
  int b = idx >> 9, j = idx & (HH-1);
  size_t r0 = (size_t)b*(3*HH);
  float gr = P0[r0+j] + P1[r0+j] + P2[r0+j] + P3[r0+j] + bih[j] + bhh[j];
  float gz = P0[r0+HH+j] + P1[r0+HH+j] + P2[r0+HH+j] + P3[r0+HH+j] + bih[HH+j] + bhh[HH+j];
  float gi = P0[r0+2*HH+j] + P1[r0+2*HH+j] + bih[2*HH+j];
  float gh = P2[r0+2*HH+j] + P3[r0+2*HH+j] + bhh[2*HH+j];
  if (xg){
    gr += xg[r0+j]; gz += xg[r0+HH+j]; gi += xg[r0+2*HH+j];
  }
  float r = 1.f/(1.f+expf(-gr));
  float z = 1.f/(1.f+expf(-gz));
  float n = tanhf(gi + r*gh);
  hnew[idx] = (1.f-z)*n + z*hprev[idx];
}

// ---------------- fc pointwise ----------------
__global__ void __launch_bounds__(256) k_pwfc(const float* __restrict__ F0,
                                              const float* __restrict__ F1,
                                              const float* __restrict__ F2,
                                              const float* __restrict__ F3,
                                              const float* __restrict__ fcb,
                                              float* __restrict__ y){
  int idx = blockIdx.x*256 + threadIdx.x;
  int j = idx & (HH-1);
  float v = F0[idx] + F1[idx] + F2[idx] + F3[idx] + fcb[j];
  y[idx] = fmaxf(v, 0.f);
}

// ---------------- attention: scores + ctx both on fp8 ----------------
__global__ void __launch_bounds__(256) k_attn(const __nv_fp8_storage_t* __restrict__ Wsf8,
                                              const __nv_fp8_storage_t* __restrict__ enf8,
                                              const float* __restrict__ UhA,
                                              const float* __restrict__ UhB,
                                              const float* __restrict__ aUb,
                                              const float* __restrict__ vw,
                                              const float* __restrict__ vb,
                                              float* __restrict__ ctx){
  __shared__ __align__(16) float us[HH];
  __shared__ __align__(16) float vs[HH];
  __shared__ __align__(16) float sc[NL];
  int b = blockIdx.x, tid = threadIdx.x;

  {
    float2 a = *(const float2*)&UhA[(size_t)b*HH + tid*2];
    float2 c = *(const float2*)&UhB[(size_t)b*HH + tid*2];
    float2 u = *(const float2*)&aUb[tid*2];
    us[tid*2]   = a.x + c.x + u.x;
    us[tid*2+1] = a.y + c.y + u.y;
    *(float2*)&vs[tid*2] = *(const float2*)&vw[tid*2];
  }
  __syncthreads();

  // scores: 2 threads per l, each 256 h of fp8 Ws (16 uint4 loads)
  {
    int l = tid >> 1, half = tid & 1;
    const uint4* wp = (const uint4*)(Wsf8 + ((size_t)(b*NL + l))*HH + half*256);
    float s = 0.f;
    #pragma unroll
    for (int i=0;i<16;i++){
      uint4 q = wp[i];
      const unsigned short* p2 = (const unsigned short*)&q;
      #pragma unroll
      for (int j=0;j<8;j++){
        float2 w = F8X2(p2[j]);
        int off = half*256 + i*16 + j*2;
        float2 u = *(const float2*)&us[off];
        float2 v = *(const float2*)&vs[off];
        s += fmaxf(w.x+u.x,0.f)*v.x + fmaxf(w.y+u.y,0.f)*v.y;
      }
    }
    s += __shfl_xor_sync(0xffffffffu, s, 1);
    if (!half) sc[l] = s + vb[0];
  }
  __syncthreads();
  if (tid < 32){
    float m = -1e30f;
    for (int l = tid; l < NL; l += 32) m = fmaxf(m, sc[l]);
    #pragma unroll
    for (int o=16;o;o>>=1) m = fmaxf(m, __shfl_xor_sync(0xffffffffu,m,o));
    float s = 0.f;
    for (int l = tid; l < NL; l += 32){ float e = expf(sc[l]-m); sc[l] = e; s += e; }
    #pragma unroll
    for (int o=16;o;o>>=1) s += __shfl_xor_sync(0xffffffffu,s,o);
    float inv = 1.f/s;
    for (int l = tid; l < NL; l += 32) sc[l] *= inv;
  }
  __syncthreads();
  // ctx: fp8 enc rows
  #pragma unroll
  for (int cc=0;cc<2;cc++){
    int c = tid + cc*256;
    const uint4* ep = (const uint4*)(enf8 + ((size_t)b*CC + c)*NL);
    float s = 0.f;
    #pragma unroll
    for (int i=0;i<8;i++){
      uint4 q = ep[i];
      const unsigned short* p2 = (const unsigned short*)&q;
      #pragma unroll
      for (int j=0;j<8;j++){
        float2 e = F8X2(p2[j]);
        float2 a = *(const float2*)&sc[i*16 + j*2];
        s += e.x*a.x + e.y*a.y;
      }
    }
    ctx[(size_t)b*CC + c] = s;
  }
}

// ---------------- per-token NLL ----------------
__global__ void __launch_bounds__(256) k_nll(const float* __restrict__ LA,
                                             const float* __restrict__ LB,
                                             const float* __restrict__ clsb,
                                             const int* __restrict__ seq,
                                             float* __restrict__ nll,
                                             float* __restrict__ msk){
  int idx = blockIdx.x*256 + threadIdx.x;
  int t = idx >> 8, b = idx & 255;
  float lg[VV];
  const float4* pa = (const float4*)(LA + (size_t)idx*VV);
  const float4* pb = (const float4*)(LB + (size_t)idx*VV);
  float m = -1e30f;
  #pragma unroll
  for (int i=0;i<16;i++){
    float4 a = pa[i], c = pb[i];
    float4 d = *(const float4*)&clsb[i*4];
    lg[i*4+0] = a.x + c.x + d.x;
    lg[i*4+1] = a.y + c.y + d.y;
    lg[i*4+2] = a.z + c.z + d.z;
    lg[i*4+3] = a.w + c.w + d.w;
  }
  #pragma unroll
  for (int v=0;v<VV;v++) m = fmaxf(m, lg[v]);
  float se = 0.f;
  #pragma unroll
  for (int v=0;v<VV;v++) se += expf(lg[v]-m);
  int label = seq[b*LSEQ + t + 1];
  float lp = lg[label] - m - logf(se);
  bool mk = label > 0;
  nll[idx] = mk ? -lp : 0.f;
  msk[idx] = mk ? 1.f : 0.f;
}

// ---------------- deterministic final reduction ----------------
__global__ void __launch_bounds__(256) k_reduce(const float* __restrict__ nll,
                                                const float* __restrict__ msk,
                                                float* __restrict__ out){
  __shared__ float sn[256], sm[256];
  int tid = threadIdx.x;
  float a = 0.f, c = 0.f;
  for (int i = tid; i < NTOK; i += 256){ a += nll[i]; c += msk[i]; }
  sn[tid] = a; sm[tid] = c;
  __syncthreads();
  for (int o = 128; o; o >>= 1){
    if (tid < o){ sn[tid] += sn[tid+o]; sm[tid] += sm[tid+o]; }
    __syncthreads();
  }
  if (tid == 0) out[0] = sn[0] / sm[0];
}

// ---------------- host orchestration (capture-time only) ----------------
extern "C" void kernel_launch(void* const* d_in, const int* in_sizes, int n_in,
                              void* d_out, int out_size){
  (void)in_sizes; (void)n_in; (void)out_size;
  const float* enc   = (const float*)d_in[0];
  const int*   seq   = (const int*)  d_in[1];
  const float* emb   = (const float*)d_in[3];
  const float* inis  = (const float*)d_in[4];
  const float* aWw   = (const float*)d_in[5];
  const float* aWb   = (const float*)d_in[6];
  const float* aUw   = (const float*)d_in[7];
  const float* aUb   = (const float*)d_in[8];
  const float* avw   = (const float*)d_in[9];
  const float* avb   = (const float*)d_in[10];
  const float* fcw   = (const float*)d_in[11];
  const float* fcb   = (const float*)d_in[12];
  const float* clsw  = (const float*)d_in[13];
  const float* clsb  = (const float*)d_in[14];
  const float* g0wih = (const float*)d_in[15];
  const float* g0whh = (const float*)d_in[16];
  const float* g0bih = (const float*)d_in[17];
  const float* g0bhh = (const float*)d_in[18];
  const float* g1wih = (const float*)d_in[19];
  const float* g1whh = (const float*)d_in[20];
  const float* g1bih = (const float*)d_in[21];
  const float* g1bhh = (const float*)d_in[22];

  __nv_bfloat16 *ench, *waWw, *waUw, *wfcw, *w0ih, *w0hh, *w1ih, *w1hh;
  __nv_fp8_storage_t *Wsf8, *enf8;
  float *xg, *xs, *ys, *y0, *h0b, *h1b, *gp0, *gp1, *fp, *Up, *ctx, *lg, *nll, *msk;
  cudaGetSymbolAddress((void**)&Wsf8, g_Wsf8);
  cudaGetSymbolAddress((void**)&ench, g_ench);
  cudaGetSymbolAddress((void**)&enf8, g_enf8);
  cudaGetSymbolAddress((void**)&waWw, g_w_aWw);
  cudaGetSymbolAddress((void**)&waUw, g_w_aUw);
  cudaGetSymbolAddress((void**)&wfcw, g_w_fcw);
  cudaGetSymbolAddress((void**)&w0ih, g_w_g0wih);
  cudaGetSymbolAddress((void**)&w0hh, g_w_g0whh);
  cudaGetSymbolAddress((void**)&w1ih, g_w_g1wih);
  cudaGetSymbolAddress((void**)&w1hh, g_w_g1whh);
  cudaGetSymbolAddress((void**)&xg,   g_xg);
  cudaGetSymbolAddress((void**)&xs,   g_xs);
  cudaGetSymbolAddress((void**)&ys,   g_ys);
  cudaGetSymbolAddress((void**)&y0,   g_y0);
  cudaGetSymbolAddress((void**)&h0b,  g_h0buf);
  cudaGetSymbolAddress((void**)&h1b,  g_h1buf);
  cudaGetSymbolAddress((void**)&gp0,  g_gp0);
  cudaGetSymbolAddress((void**)&gp1,  g_gp1);
  cudaGetSymbolAddress((void**)&fp,   g_fp);
  cudaGetSymbolAddress((void**)&Up,   g_Up);
  cudaGetSymbolAddress((void**)&ctx,  g_ctx);
  cudaGetSymbolAddress((void**)&lg,   g_lg);
  cudaGetSymbolAddress((void**)&nll,  g_nll);
  cudaGetSymbolAddress((void**)&msk,  g_msk);

  const size_t GSZ = (size_t)BB*3*HH;
  float* GP0[4] = {gp0, gp0+GSZ, gp0+2*GSZ, gp0+3*GSZ};
  float* GP1[4] = {gp1, gp1+GSZ, gp1+2*GSZ, gp1+3*GSZ};
  float* FP[4] = {fp, fp+BH, fp+2*BH, fp+3*BH};
  float* UP[2] = {Up, Up+BH};
  float* LG[2] = {lg, lg+(size_t)NTOK*VV};

  // stream/events created ONCE (first call = correctness run, pre-baseline)
  static cudaStream_t sB = nullptr;
  static cudaEvent_t evFork, ev0h, ev1h, evpw0, evpw1;
  if (!sB){
    cudaStreamCreateWithFlags(&sB, cudaStreamNonBlocking);
    cudaEventCreateWithFlags(&evFork, cudaEventDisableTiming);
    cudaEventCreateWithFlags(&ev0h,  cudaEventDisableTiming);
    cudaEventCreateWithFlags(&ev1h,  cudaEventDisableTiming);
    cudaEventCreateWithFlags(&evpw0, cudaEventDisableTiming);
    cudaEventCreateWithFlags(&evpw1, cudaEventDisableTiming);
  }

  // one-time precompute (main stream)
  k_inith<<<(BH+255)/256, 256>>>(inis, h0b, h1b);
  k_embed<<<(TT*BH+255)/256, 256>>>(emb, seq, xs);
  k_tobf16<<<(BB*CC*NL/4+255)/256, 256>>>(enc, ench, BB*CC*NL/4);
  k_tofp8<<<(BB*CC*NL/4+255)/256, 256>>>(enc, enf8, BB*CC*NL/4);
  k_tobf16<<<(HH*CC/4+255)/256, 256>>>(aWw, waWw, HH*CC/4);
  k_tobf16<<<(HH*HH/4+255)/256, 256>>>(aUw, waUw, HH*HH/4);
  k_tobf16<<<(HH*(CC+HH)/4+255)/256, 256>>>(fcw, wfcw, HH*(CC+HH)/4);
  k_tobf16<<<(3*HH*2*HH/4+255)/256, 256>>>(g0wih, w0ih, 3*HH*2*HH/4);
  k_tobf16<<<(3*HH*HH/4+255)/256, 256>>>(g0whh, w0hh, 3*HH*HH/4);
  k_tobf16<<<(3*HH*HH/4+255)/256, 256>>>(g1wih, w1ih, 3*HH*HH/4);
  k_tobf16<<<(3*HH*HH/4+255)/256, 256>>>(g1whh, w1hh, 3*HH*HH/4);
  k_wsT<<<dim3(512, 4), 256>>>(ench, waWw, aWb, Wsf8);
  k_mmT<<<dim3(92, 12, 1), 256>>>(xs, 512, w0ih, 1024, 512,
                                  xs, 512, w0ih, 1024, 512,
                                  1, 512, xg, 3*HH);

  auto attn_fc = [&](const float* h1cur, float* yout){
    k_mmT<<<dim3(4, 4, 2), 256>>>(h1cur, HH, waUw, 512, 0,
                                  h1cur, HH, waUw, 512, 0,
                                  2, 256, Up, HH);
    k_attn<<<BB, 256>>>(Wsf8, enf8, UP[0], UP[1], aUb, avw, avb, ctx);
    k_mmT<<<dim3(4, 4, 4), 256>>>(ctx, CC, wfcw, 1024, 0,
                                  h1cur, HH, wfcw, 1024, 512,
                                  2, 256, fp, HH);
    k_pwfc<<<BH/256, 256>>>(FP[0], FP[1], FP[2], FP[3], fcb, yout);
  };

  // y0 on main
  attn_fc(h1b, y0);

  // fork sB: h-recurrent gate halves for t=0
  cudaEventRecord(evFork, 0);
  cudaStreamWaitEvent(sB, evFork, 0);
  k_mmT<<<dim3(4, 12, 2), 256, 0, sB>>>(h0b, HH, w0hh, 512, 0,
                                        h0b, HH, w0hh, 512, 0,
                                        2, 256, GP0[2], 3*HH);
  cudaEventRecord(ev0h, sB);
  k_mmT<<<dim3(4, 12, 2), 256, 0, sB>>>(h1b, HH, w1hh, 512, 0,
                                        h1b, HH, w1hh, 512, 0,
                                        2, 256, GP1[2], 3*HH);
  cudaEventRecord(ev1h, sB);

  const float* yprev = y0;
  for (int t = 0; t < TT; t++){
    float* h0r = h0b + (size_t)(t & 1)*BH;
    float* h0w = h0b + (size_t)((t+1) & 1)*BH;
    float* h1r = h1b + (size_t)(t & 1)*BH;
    float* h1w = h1b + (size_t)((t+1) & 1)*BH;

    // GRU0 input half (critical path)
    k_mmT<<<dim3(4, 12, 2), 256>>>(yprev, HH, w0ih, 1024, 0,
                                   yprev, HH, w0ih, 1024, 0,
                                   2, 256, GP0[0], 3*HH);
    cudaStreamWaitEvent(0, ev0h, 0);
    k_pw<<<BH/256, 256>>>(GP0[0], GP0[1], GP0[2], GP0[3],
                          xg + (size_t)t*GSZ, h0r, g0bih, g0bhh, h0w);
    if (t+1 < TT){
      cudaEventRecord(evpw0, 0);
      cudaStreamWaitEvent(sB, evpw0, 0);
      k_mmT<<<dim3(4, 12, 2), 256, 0, sB>>>(h0w, HH, w0hh, 512, 0,
                                            h0w, HH, w0hh, 512, 0,
                                            2, 256, GP0[2], 3*HH);
      cudaEventRecord(ev0h, sB);
    }

    // GRU1 input half
    k_mmT<<<dim3(4, 12, 2), 256>>>(h0w, HH, w1ih, 512, 0,
                                   h0w, HH, w1ih, 512, 0,
                                   2, 256, GP1[0], 3*HH);
    cudaStreamWaitEvent(0, ev1h, 0);
    k_pw<<<BH/256, 256>>>(GP1[0], GP1[1], GP1[2], GP1[3],
                          (const float*)nullptr, h1r, g1bih, g1bhh, h1w);
    if (t+1 < TT){
      cudaEventRecord(evpw1, 0);
      cudaStreamWaitEvent(sB, evpw1, 0);
      k_mmT<<<dim3(4, 12, 2), 256, 0, sB>>>(h1w, HH, w1hh, 512, 0,
                                            h1w, HH, w1hh, 512, 0,
                                            2, 256, GP1[2], 3*HH);
      cudaEventRecord(ev1h, sB);
    }

    // attention + out_proj (main)
    attn_fc(h1w, ys + (size_t)t*BH);
    yprev = ys + (size_t)t*BH;
  }

  // logits + NLL + reduce (main)
  k_g64<<<dim3(92, 1, 2), 256>>>(ys, HH, clsw, 512, 0, LG[0], LG[1], VV);
  k_nll<<<NTOK/256, 256>>>(LG[0], LG[1], clsb, seq, nll, msk);
  k_reduce<<<1, 256>>>(nll, msk, (float*)d_out);
}

// round 17
// speedup vs baseline: 1.2330x; 1.0140x over previous
#include <cuda_runtime.h>
#include <cuda_bf16.h>
#include <cuda_fp8.h>
#include <math.h>

#define BB 256
#define HH 512
#define CC 512
#define NL 128
#define TT 23
#define LSEQ 24
#define VV 64
#define BH (BB*HH)
#define NTOK (TT*BB)
#define KC 32
#define ASTR 40

typedef unsigned long long u64;
typedef unsigned int u32;

__device__ __forceinline__ void MMA16816(float &d0, float &d1, float &d2, float &d3,
                                         u32 a0, u32 a1, u32 a2, u32 a3,
                                         u32 b0, u32 b1){
  asm volatile("mma.sync.aligned.m16n8k16.row.col.f32.bf16.bf16.f32 "
               "{%0,%1,%2,%3},{%4,%5,%6,%7},{%8,%9},{%0,%1,%2,%3};"
               : "+f"(d0), "+f"(d1), "+f"(d2), "+f"(d3)
               : "r"(a0), "r"(a1), "r"(a2), "r"(a3), "r"(b0), "r"(b1));
}
__device__ __forceinline__ u32 BF2U(__nv_bfloat162 v){ return *reinterpret_cast<u32*>(&v); }
__device__ __forceinline__ void FMA2(u64 &d, u64 a, u64 b){
  asm("fma.rn.f32x2 %0, %1, %2, %0;" : "+l"(d) : "l"(a), "l"(b));
}
__device__ __forceinline__ u64 PACK2(float x, float y){
  u64 r; asm("mov.b64 %0, {%1, %2};" : "=l"(r) : "f"(x), "f"(y)); return r;
}
__device__ __forceinline__ float2 UNPK(u64 v){
  float2 r; asm("mov.b64 {%0, %1}, %2;" : "=f"(r.x), "=f"(r.y) : "l"(v)); return r;
}
__device__ __forceinline__ float2 F8X2(unsigned short v){
  __half2_raw h = __nv_cvt_fp8x2_to_halfraw2(v, __NV_E4M3);
  return __half22float2(*(__half2*)&h);
}

// ---------------- static scratch ----------------
__device__ __nv_fp8_storage_t g_Wsf8[(size_t)BB*NL*HH];
__device__ __nv_fp8_storage_t g_enf8[(size_t)BB*CC*NL];
__device__ __nv_bfloat16 g_w_aWw[HH*CC];
__device__ __nv_bfloat16 g_w_aUw[HH*HH];
__device__ __nv_bfloat16 g_w_fcw[HH*(CC+HH)];
__device__ __nv_bfloat16 g_w_g0wih[3*HH*2*HH];
__device__ __nv_bfloat16 g_w_g0whh[3*HH*HH];
__device__ __nv_bfloat16 g_w_g1wih[3*HH*HH];
__device__ __nv_bfloat16 g_w_g1whh[3*HH*HH];
__device__ float g_xg[(size_t)TT*BB*3*HH];
__device__ float g_xs[(size_t)TT*BH];
__device__ float g_ys[(size_t)TT*BH];
__device__ float g_y0[BH];
__device__ float g_h0buf[2][BH];
__device__ float g_h1buf[2][BH];
__device__ float g_gp0[4][(size_t)BB*3*HH];
__device__ float g_gp1[4][(size_t)BB*3*HH];
__device__ float g_fp[4][BH];
__device__ float g_Up[2][BH];
__device__ float g_ctx[BH];
__device__ float g_lgt[(size_t)NTOK*VV];
__device__ float g_nll[NTOK];
__device__ float g_msk[NTOK];

// ---------------- init / embed / convert ----------------
__global__ void k_inith(const float* __restrict__ init_state,
                        float* __restrict__ h0, float* __restrict__ h1){
  int idx = blockIdx.x*blockDim.x + threadIdx.x;
  if (idx < BH){
    int j = idx & (HH-1);
    h0[idx] = init_state[j];
    h1[idx] = init_state[HH + j];
  }
}

__global__ void k_embed(const float* __restrict__ emb, const int* __restrict__ seq,
                        float* __restrict__ xs){
  int idx = blockIdx.x*blockDim.x + threadIdx.x;
  if (idx < TT*BH){
    int h = idx & (HH-1);
    int r = idx >> 9;
    int b = r & (BB-1);
    int t = r >> 8;
    int tok = seq[b*LSEQ + t];
    xs[idx] = emb[(size_t)tok*HH + h];
  }
}

__global__ void k_tobf16(const float* __restrict__ in, __nv_bfloat16* __restrict__ out, int n4){
  int idx = blockIdx.x*blockDim.x + threadIdx.x;
  if (idx < n4){
    float4 v = *(const float4*)&in[(size_t)idx*4];
    *(__nv_bfloat162*)&out[(size_t)idx*4]   = __floats2bfloat162_rn(v.x, v.y);
    *(__nv_bfloat162*)&out[(size_t)idx*4+2] = __floats2bfloat162_rn(v.z, v.w);
  }
}

__global__ void k_tofp8(const float* __restrict__ in, __nv_fp8_storage_t* __restrict__ out, int n4){
  int idx = blockIdx.x*blockDim.x + threadIdx.x;
  if (idx < n4){
    float4 v = *(const float4*)&in[(size_t)idx*4];
    u32 lo = __nv_cvt_float2_to_fp8x2(make_float2(v.x, v.y), __NV_SATFINITE, __NV_E4M3);
    u32 hi = __nv_cvt_float2_to_fp8x2(make_float2(v.z, v.w), __NV_SATFINITE, __NV_E4M3);
    *(u32*)&out[(size_t)idx*4] = lo | (hi << 16);
  }
}

// ============ 64x128 mma frag pattern (8 warps of 32x32) ============
#define MMA_FRAGS(AtP, WtP)                                                    \
  _Pragma("unroll")                                                            \
  for (int k16 = 0; k16 < KC; k16 += 16){                                      \
    u32 af[2][4]; u32 bfv[4][2];                                               \
    _Pragma("unroll")                                                          \
    for (int mt = 0; mt < 2; mt++){                                            \
      int r = wm + mt*16 + gid;                                                \
      af[mt][0] = *(const u32*)&(AtP)[r*ASTR      + k16 + tig*2];              \
      af[mt][1] = *(const u32*)&(AtP)[(r+8)*ASTR  + k16 + tig*2];              \
      af[mt][2] = *(const u32*)&(AtP)[r*ASTR      + k16 + tig*2 + 8];          \
      af[mt][3] = *(const u32*)&(AtP)[(r+8)*ASTR  + k16 + tig*2 + 8];          \
    }                                                                          \
    _Pragma("unroll")                                                          \
    for (int nt = 0; nt < 4; nt++){                                            \
      int r = wn + nt*8 + gid;                                                 \
      bfv[nt][0] = *(const u32*)&(WtP)[r*ASTR + k16 + tig*2];                  \
      bfv[nt][1] = *(const u32*)&(WtP)[r*ASTR + k16 + tig*2 + 8];              \
    }                                                                          \
    _Pragma("unroll")                                                          \
    for (int mt = 0; mt < 2; mt++)                                             \
      _Pragma("unroll")                                                        \
      for (int nt = 0; nt < 4; nt++)                                           \
        MMA16816(acc[mt][nt][0], acc[mt][nt][1], acc[mt][nt][2], acc[mt][nt][3],\
                 af[mt][0], af[mt][1], af[mt][2], af[mt][3],                   \
                 bfv[nt][0], bfv[nt][1]);                                      \
  }

// ---------------- generic mma GEMM (2 sets, K-sliced partials) ----------------
__global__ void __launch_bounds__(256) k_mmT(
    const float* __restrict__ A0, int wA0,
    const __nv_bfloat16* __restrict__ W0, int s0, int o0,
    const float* __restrict__ A1, int wA1,
    const __nv_bfloat16* __restrict__ W1, int s1, int o1,
    int zPerSet, int kSlice, float* __restrict__ Cb, int ldc){
  __shared__ __align__(16) __nv_bfloat16 At[2][64*ASTR];
  __shared__ __align__(16) __nv_bfloat16 Wt[2][128*ASTR];
  int z = blockIdx.z;
  int set = z / zPerSet;
  int kb = (z - set*zPerSet) * kSlice;
  const float* A = set ? A1 : A0;
  const __nv_bfloat16* W = set ? W1 : W0;
  int wA = set ? wA1 : wA0;
  int s  = set ? s1 : s0;
  int o  = set ? o1 : o0;
  int M = gridDim.x * 64;
  float* C = Cb + (size_t)z * M * ldc;

  int m0 = blockIdx.x*64, n0 = blockIdx.y*128;
  int tid = threadIdx.x;
  int warp = tid >> 5, lane = tid & 31;
  int wm = (warp & 1)*32, wn = (warp >> 1)*32;
  int gid = lane >> 2, tig = lane & 3;
  float acc[2][4][4] = {};

  float4 ra[2]; uint4 rw[2];
  auto loadT = [&](int t){
    int kc = kb + t*KC;
    #pragma unroll
    for (int i=0;i<2;i++){
      int idx = tid + i*256;
      int r = idx >> 3, k4 = (idx & 7)*4;
      ra[i] = *(const float4*)&A[(size_t)(m0+r)*wA + kc + k4];
      int rr = idx >> 2, k8 = (idx & 3)*8;
      rw[i] = *(const uint4*)&W[(size_t)(n0+rr)*s + o + kc + k8];
    }
  };
  auto storeT = [&](int buf){
    #pragma unroll
    for (int i=0;i<2;i++){
      int idx = tid + i*256;
      int r = idx >> 3, k4 = (idx & 7)*4;
      u32 p0 = BF2U(__floats2bfloat162_rn(ra[i].x, ra[i].y));
      u32 p1 = BF2U(__floats2bfloat162_rn(ra[i].z, ra[i].w));
      *(uint2*)&At[buf][r*ASTR + k4] = make_uint2(p0, p1);
      int rr = idx >> 2, k8 = (idx & 3)*8;
      *(uint4*)&Wt[buf][rr*ASTR + k8] = rw[i];
    }
  };

  int ntc = kSlice / KC;
  loadT(0); storeT(0); __syncthreads();
  for (int t=0;t<ntc;t++){
    int buf = t & 1;
    if (t+1 < ntc) loadT(t+1);
    MMA_FRAGS(At[buf], Wt[buf])
    if (t+1 < ntc) storeT((t+1)&1);
    __syncthreads();
  }

  #pragma unroll
  for (int mt=0;mt<2;mt++){
    #pragma unroll
    for (int nt=0;nt<4;nt++){
      int m = m0 + wm + mt*16 + gid;
      int n = n0 + wn + nt*8 + tig*2;
      *(float2*)&C[(size_t)m*ldc + n]     = make_float2(acc[mt][nt][0], acc[mt][nt][1]);
      *(float2*)&C[(size_t)(m+8)*ldc + n] = make_float2(acc[mt][nt][2], acc[mt][nt][3]);
    }
  }
}

// ---------------- Ws GEMM (fp8 enc A, fp8 out) ----------------
__global__ void __launch_bounds__(256) k_wsT(
    const __nv_fp8_storage_t* __restrict__ enf8,
    const __nv_bfloat16* __restrict__ Wwb,
    const float* __restrict__ Wb,
    __nv_fp8_storage_t* __restrict__ Wsf8){
  __shared__ __align__(16) __nv_bfloat16 At2[2][64*ASTR];
  __shared__ __align__(16) __nv_bfloat16 Wt2[2][128*ASTR];
  int m0 = blockIdx.x*64;
  int b = m0 >> 7, l0 = m0 & 127;
  int n0 = blockIdx.y*128;
  int tid = threadIdx.x;
  int warp = tid >> 5, lane = tid & 31;
  int wm = (warp & 1)*32, wn = (warp >> 1)*32;
  int gid = lane >> 2, tig = lane & 3;
  float acc[2][4][4] = {};

  uint2 raw8; uint4 rw[2];
  int ak = tid >> 3, al8 = (tid & 7)*8;

  auto loadT = [&](int t){
    int kc = t*KC;
    raw8 = *(const uint2*)&enf8[(size_t)b*CC*NL + (size_t)(kc+ak)*NL + l0 + al8];
    #pragma unroll
    for (int i=0;i<2;i++){
      int idx = tid + i*256;
      int rr = idx >> 2, k8 = (idx & 3)*8;
      rw[i] = *(const uint4*)&Wwb[(size_t)(n0+rr)*CC + kc + k8];
    }
  };
  auto storeT = [&](int buf){
    const unsigned short* pr = (const unsigned short*)&raw8;
    #pragma unroll
    for (int i=0;i<4;i++){
      float2 e = F8X2(pr[i]);
      At2[buf][(al8+i*2)*ASTR + ak]   = __float2bfloat16(e.x);
      At2[buf][(al8+i*2+1)*ASTR + ak] = __float2bfloat16(e.y);
    }
    #pragma unroll
    for (int i=0;i<2;i++){
      int idx = tid + i*256;
      int rr = idx >> 2, k8 = (idx & 3)*8;
      *(uint4*)&Wt2[buf][rr*ASTR + k8] = rw[i];
    }
  };

  loadT(0); storeT(0); __syncthreads();
  for (int t=0;t<16;t++){
    int buf = t & 1;
    if (t+1 < 16) loadT(t+1);
    MMA_FRAGS(At2[buf], Wt2[buf])
    if (t+1 < 16) storeT((t+1)&1);
    __syncthreads();
  }

  #pragma unroll
  for (int mt=0;mt<2;mt++){
    #pragma unroll
    for (int nt=0;nt<4;nt++){
      int m = m0 + wm + mt*16 + gid;
      int n = n0 + wn + nt*8 + tig*2;
      float2 bi = *(const float2*)&Wb[n];
      unsigned short lo = __nv_cvt_float2_to_fp8x2(
          make_float2(acc[mt][nt][0]+bi.x, acc[mt][nt][1]+bi.y),
          __NV_SATFINITE, __NV_E4M3);
      unsigned short hi = __nv_cvt_float2_to_fp8x2(
          make_float2(acc[mt][nt][2]+bi.x, acc[mt][nt][3]+bi.y),
          __NV_SATFINITE, __NV_E4M3);
      *(unsigned short*)&Wsf8[(size_t)m*HH + n]     = lo;
      *(unsigned short*)&Wsf8[(size_t)(m+8)*HH + n] = hi;
    }
  }
}

// ---------------- logits GEMM: bf16 mma, 64x64 tile, fused bias ----------------
__global__ void __launch_bounds__(256) k_gl(
    const float* __restrict__ A0,       // ys [M,512]
    const float* __restrict__ W0,       // clsw [64,512]
    const float* __restrict__ bias,     // clsb
    float* __restrict__ C){             // [M,64]
  __shared__ __align__(16) __nv_bfloat16 At[2][64*ASTR];
  __shared__ __align__(16) __nv_bfloat16 Wt[2][64*ASTR];
  int m0 = blockIdx.x*64;
  int tid = threadIdx.x;
  int warp = tid >> 5, lane = tid & 31;
  int wm = (warp & 3)*16, wn = (warp >> 2)*32;
  int gid = lane >> 2, tig = lane & 3;
  float acc[4][4] = {};

  float4 ra[2], rwv[2];
  auto loadT = [&](int t){
    int kc = t*KC;
    #pragma unroll
    for (int i=0;i<2;i++){
      int idx = tid + i*256;
      int r = idx >> 3, k4 = (idx & 7)*4;
      ra[i]  = *(const float4*)&A0[(size_t)(m0+r)*HH + kc + k4];
      rwv[i] = *(const float4*)&W0[(size_t)r*HH + kc + k4];
    }
  };
  auto storeT = [&](int buf){
    #pragma unroll
    for (int i=0;i<2;i++){
      int idx = tid + i*256;
      int r = idx >> 3, k4 = (idx & 7)*4;
      u32 a0p = BF2U(__floats2bfloat162_rn(ra[i].x, ra[i].y));
      u32 a1p = BF2U(__floats2bfloat162_rn(ra[i].z, ra[i].w));
      *(uint2*)&At[buf][r*ASTR + k4] = make_uint2(a0p, a1p);
      u32 w0p = BF2U(__floats2bfloat162_rn(rwv[i].x, rwv[i].y));
      u32 w1p = BF2U(__floats2bfloat162_rn(rwv[i].z, rwv[i].w));
      *(uint2*)&Wt[buf][r*ASTR + k4] = make_uint2(w0p, w1p);
    }
  };

  loadT(0); storeT(0); __syncthreads();
  for (int t=0;t<16;t++){
    int buf = t & 1;
    if (t+1 < 16) loadT(t+1);
    #pragma unroll
    for (int k16=0;k16<KC;k16+=16){
      u32 af0 = *(const u32*)&At[buf][(wm+gid)*ASTR + k16 + tig*2];
      u32 af1 = *(const u32*)&At[buf][(wm+gid+8)*ASTR + k16 + tig*2];
      u32 af2 = *(const u32*)&At[buf][(wm+gid)*ASTR + k16 + tig*2 + 8];
      u32 af3 = *(const u32*)&At[buf][(wm+gid+8)*ASTR + k16 + tig*2 + 8];
      #pragma unroll
      for (int nt=0;nt<4;nt++){
        u32 b0 = *(const u32*)&Wt[buf][(wn+nt*8+gid)*ASTR + k16 + tig*2];
        u32 b1 = *(const u32*)&Wt[buf][(wn+nt*8+gid)*ASTR + k16 + tig*2 + 8];
        MMA16816(acc[nt][0],acc[nt][1],acc[nt][2],acc[nt][3],
                 af0,af1,af2,af3, b0,b1);
      }
    }
    if (t+1 < 16) storeT((t+1)&1);
    __syncthreads();
  }

  #pragma unroll
  for (int nt=0;nt<4;nt++){
    int m = m0 + wm + gid;
    int n = wn + nt*8 + tig*2;
    float2 bi = *(const float2*)&bias[n];
    *(float2*)&C[(size_t)m*VV + n]     = make_float2(acc[nt][0]+bi.x, acc[nt][1]+bi.y);
    *(float2*)&C[(size_t)(m+8)*VV + n] = make_float2(acc[nt][2]+bi.x, acc[nt][3]+bi.y);
  }
}

// ---------------- GRU pointwise: combine 4 gate partials ----------------
__global__ void __launch_bounds__(256) k_pw(const float* __restrict__ P0,
                                            const float* __restrict__ P1,
                                            const float* __restrict__ P2,
                                            const float* __restrict__ P3,
                                            const float* __restrict__ xg,
                                            const float* __restrict__ hprev,
                                            const float* __restrict__ bih,
                                            const float* __restrict__ bhh,
                                            float* __restrict__ hnew){
  int idx = blockIdx.x*256 + threadIdx.x;
  int b = idx >> 9, j = idx & (HH-1);
  size_t r0 = (size_t)b*(3*HH);
  float gr = P0[r0+j] + P1[r0+j] + P2[r0+j] + P3[r0+j] + bih[j] + bhh[j];
  float gz = P0[r0+HH+j] + P1[r0+HH+j] + P2[r0+HH+j] + P3[r0+HH+j] + bih[HH+j] + bhh[HH+j];
  float gi = P0[r0+2*HH+j] + P1[r0+2*HH+j] + bih[2*HH+j];
  float gh = P2[r0+2*HH+j] + P3[r0+2*HH+j] + bhh[2*HH+j];
  if (xg){
    gr += xg[r0+j]; gz += xg[r0+HH+j]; gi += xg[r0+2*HH+j];
  }
  float r = 1.f/(1.f+expf(-gr));
  float z = 1.f/(1.f+expf(-gz));
  float n = tanhf(gi + r*gh);
  hnew[idx] = (1.f-z)*n + z*hprev[idx];
}

// ---------------- fc pointwise ----------------
__global__ void __launch_bounds__(256) k_pwfc(const float* __restrict__ F0,
                                              const float* __restrict__ F1,
                                              const float* __restrict__ F2,
                                              const float* __restrict__ F3,
                                              const float* __restrict__ fcb,
                                              float* __restrict__ y){
  int idx = blockIdx.x*256 + threadIdx.x;
  int j = idx & (HH-1);
  float v = F0[idx] + F1[idx] + F2[idx] + F3[idx] + fcb[j];
  y[idx] = fmaxf(v, 0.f);
}

// ---------------- attention: scores + ctx both on fp8 ----------------
__global__ void __launch_bounds__(256) k_attn(const __nv_fp8_storage_t* __restrict__ Wsf8,
                                              const __nv_fp8_storage_t* __restrict__ enf8,
                                              const float* __restrict__ UhA,
                                              const float* __restrict__ UhB,
                                              const float* __restrict__ aUb,
                                              const float* __restrict__ vw,
                                              const float* __restrict__ vb,
                                              float* __restrict__ ctx){
  __shared__ __align__(16) float us[HH];
  __shared__ __align__(16) float vs[HH];
  __shared__ __align__(16) float sc[NL];
  int b = blockIdx.x, tid = threadIdx.x;

  {
    float2 a = *(const float2*)&UhA[(size_t)b*HH + tid*2];
    float2 c = *(const float2*)&UhB[(size_t)b*HH + tid*2];
    float2 u = *(const float2*)&aUb[tid*2];
    us[tid*2]   = a.x + c.x + u.x;
    us[tid*2+1] = a.y + c.y + u.y;
    *(float2*)&vs[tid*2] = *(const float2*)&vw[tid*2];
  }
  __syncthreads();

  {
    int l = tid >> 1, half = tid & 1;
    const uint4* wp = (const uint4*)(Wsf8 + ((size_t)(b*NL + l))*HH + half*256);
    float s = 0.f;
    #pragma unroll
    for (int i=0;i<16;i++){
      uint4 q = wp[i];
      const unsigned short* p2 = (const unsigned short*)&q;
      #pragma unroll
      for (int j=0;j<8;j++){
        float2 w = F8X2(p2[j]);
        int off = half*256 + i*16 + j*2;
        float2 u = *(const float2*)&us[off];
        float2 v = *(const float2*)&vs[off];
        s += fmaxf(w.x+u.x,0.f)*v.x + fmaxf(w.y+u.y,0.f)*v.y;
      }
    }
    s += __shfl_xor_sync(0xffffffffu, s, 1);
    if (!half) sc[l] = s + vb[0];
  }
  __syncthreads();
  if (tid < 32){
    float m = -1e30f;
    for (int l = tid; l < NL; l += 32) m = fmaxf(m, sc[l]);
    #pragma unroll
    for (int o=16;o;o>>=1) m = fmaxf(m, __shfl_xor_sync(0xffffffffu,m,o));
    float s = 0.f;
    for (int l = tid; l < NL; l += 32){ float e = expf(sc[l]-m); sc[l] = e; s += e; }
    #pragma unroll
    for (int o=16;o;o>>=1) s += __shfl_xor_sync(0xffffffffu,s,o);
    float inv = 1.f/s;
    for (int l = tid; l < NL; l += 32) sc[l] *= inv;
  }
  __syncthreads();
  #pragma unroll
  for (int cc=0;cc<2;cc++){
    int c = tid + cc*256;
    const uint4* ep = (const uint4*)(enf8 + ((size_t)b*CC + c)*NL);
    float s = 0.f;
    #pragma unroll
    for (int i=0;i<8;i++){
      uint4 q = ep[i];
      const unsigned short* p2 = (const unsigned short*)&q;
      #pragma unroll
      for (int j=0;j<8;j++){
        float2 e = F8X2(p2[j]);
        float2 a = *(const float2*)&sc[i*16 + j*2];
        s += e.x*a.x + e.y*a.y;
      }
    }
    ctx[(size_t)b*CC + c] = s;
  }
}

// ---------------- per-token NLL (logits already biased) ----------------
__global__ void __launch_bounds__(256) k_nll(const float* __restrict__ L,
                                             const int* __restrict__ seq,
                                             float* __restrict__ nll,
                                             float* __restrict__ msk){
  int idx = blockIdx.x*256 + threadIdx.x;
  int t = idx >> 8, b = idx & 255;
  float lg[VV];
  const float4* pa = (const float4*)(L + (size_t)idx*VV);
  #pragma unroll
  for (int i=0;i<16;i++){
    float4 a = pa[i];
    lg[i*4+0] = a.x; lg[i*4+1] = a.y; lg[i*4+2] = a.z; lg[i*4+3] = a.w;
  }
  float m = -1e30f;
  #pragma unroll
  for (int v=0;v<VV;v++) m = fmaxf(m, lg[v]);
  float se = 0.f;
  #pragma unroll
  for (int v=0;v<VV;v++) se += expf(lg[v]-m);
  int label = seq[b*LSEQ + t + 1];
  float lp = lg[label] - m - logf(se);
  bool mk = label > 0;
  nll[idx] = mk ? -lp : 0.f;
  msk[idx] = mk ? 1.f : 0.f;
}

// ---------------- deterministic final reduction ----------------
__global__ void __launch_bounds__(256) k_reduce(const float* __restrict__ nll,
                                                const float* __restrict__ msk,
                                                float* __restrict__ out){
  __shared__ float sn[256], sm[256];
  int tid = threadIdx.x;
  float a = 0.f, c = 0.f;
  for (int i = tid; i < NTOK; i += 256){ a += nll[i]; c += msk[i]; }
  sn[tid] = a; sm[tid] = c;
  __syncthreads();
  for (int o = 128; o; o >>= 1){
    if (tid < o){ sn[tid] += sn[tid+o]; sm[tid] += sm[tid+o]; }
    __syncthreads();
  }
  if (tid == 0) out[0] = sn[0] / sm[0];
}

// ---------------- host orchestration (capture-time only) ----------------
extern "C" void kernel_launch(void* const* d_in, const int* in_sizes, int n_in,
                              void* d_out, int out_size){
  (void)in_sizes; (void)n_in; (void)out_size;
  const float* enc   = (const float*)d_in[0];
  const int*   seq   = (const int*)  d_in[1];
  const float* emb   = (const float*)d_in[3];
  const float* inis  = (const float*)d_in[4];
  const float* aWw   = (const float*)d_in[5];
  const float* aWb   = (const float*)d_in[6];
  const float* aUw   = (const float*)d_in[7];
  const float* aUb   = (const float*)d_in[8];
  const float* avw   = (const float*)d_in[9];
  const float* avb   = (const float*)d_in[10];
  const float* fcw   = (const float*)d_in[11];
  const float* fcb   = (const float*)d_in[12];
  const float* clsw  = (const float*)d_in[13];
  const float* clsb  = (const float*)d_in[14];
  const float* g0wih = (const float*)d_in[15];
  const float* g0whh = (const float*)d_in[16];
  const float* g0bih = (const float*)d_in[17];
  const float* g0bhh = (const float*)d_in[18];
  const float* g1wih = (const float*)d_in[19];
  const float* g1whh = (const float*)d_in[20];
  const float* g1bih = (const float*)d_in[21];
  const float* g1bhh = (const float*)d_in[22];

  __nv_bfloat16 *waWw, *waUw, *wfcw, *w0ih, *w0hh, *w1ih, *w1hh;
  __nv_fp8_storage_t *Wsf8, *enf8;
  float *xg, *xs, *ys, *y0, *h0b, *h1b, *gp0, *gp1, *fp, *Up, *ctx, *lgt, *nll, *msk;
  cudaGetSymbolAddress((void**)&Wsf8, g_Wsf8);
  cudaGetSymbolAddress((void**)&enf8, g_enf8);
  cudaGetSymbolAddress((void**)&waWw, g_w_aWw);
  cudaGetSymbolAddress((void**)&waUw, g_w_aUw);
  cudaGetSymbolAddress((void**)&wfcw, g_w_fcw);
  cudaGetSymbolAddress((void**)&w0ih, g_w_g0wih);
  cudaGetSymbolAddress((void**)&w0hh, g_w_g0whh);
  cudaGetSymbolAddress((void**)&w1ih, g_w_g1wih);
  cudaGetSymbolAddress((void**)&w1hh, g_w_g1whh);
  cudaGetSymbolAddress((void**)&xg,   g_xg);
  cudaGetSymbolAddress((void**)&xs,   g_xs);
  cudaGetSymbolAddress((void**)&ys,   g_ys);
  cudaGetSymbolAddress((void**)&y0,   g_y0);
  cudaGetSymbolAddress((void**)&h0b,  g_h0buf);
  cudaGetSymbolAddress((void**)&h1b,  g_h1buf);
  cudaGetSymbolAddress((void**)&gp0,  g_gp0);
  cudaGetSymbolAddress((void**)&gp1,  g_gp1);
  cudaGetSymbolAddress((void**)&fp,   g_fp);
  cudaGetSymbolAddress((void**)&Up,   g_Up);
  cudaGetSymbolAddress((void**)&ctx,  g_ctx);
  cudaGetSymbolAddress((void**)&lgt,  g_lgt);
  cudaGetSymbolAddress((void**)&nll,  g_nll);
  cudaGetSymbolAddress((void**)&msk,  g_msk);

  const size_t GSZ = (size_t)BB*3*HH;
  float* GP0[4] = {gp0, gp0+GSZ, gp0+2*GSZ, gp0+3*GSZ};
  float* GP1[4] = {gp1, gp1+GSZ, gp1+2*GSZ, gp1+3*GSZ};
  float* FP[4] = {fp, fp+BH, fp+2*BH, fp+3*BH};
  float* UP[2] = {Up, Up+BH};

  // stream/events created ONCE (first call = correctness run, pre-baseline)
  static cudaStream_t sB = nullptr;
  static cudaEvent_t evFork, ev0h, ev1h, evpw0, evpw1;
  if (!sB){
    cudaStreamCreateWithFlags(&sB, cudaStreamNonBlocking);
    cudaEventCreateWithFlags(&evFork, cudaEventDisableTiming);
    cudaEventCreateWithFlags(&ev0h,  cudaEventDisableTiming);
    cudaEventCreateWithFlags(&ev1h,  cudaEventDisableTiming);
    cudaEventCreateWithFlags(&evpw0, cudaEventDisableTiming);
    cudaEventCreateWithFlags(&evpw1, cudaEventDisableTiming);
  }

  // one-time precompute (main stream)
  k_inith<<<(BH+255)/256, 256>>>(inis, h0b, h1b);
  k_embed<<<(TT*BH+255)/256, 256>>>(emb, seq, xs);
  k_tofp8<<<(BB*CC*NL/4+255)/256, 256>>>(enc, enf8, BB*CC*NL/4);
  k_tobf16<<<(HH*CC/4+255)/256, 256>>>(aWw, waWw, HH*CC/4);
  k_tobf16<<<(HH*HH/4+255)/256, 256>>>(aUw, waUw, HH*HH/4);
  k_tobf16<<<(HH*(CC+HH)/4+255)/256, 256>>>(fcw, wfcw, HH*(CC+HH)/4);
  k_tobf16<<<(3*HH*2*HH/4+255)/256, 256>>>(g0wih, w0ih, 3*HH*2*HH/4);
  k_tobf16<<<(3*HH*HH/4+255)/256, 256>>>(g0whh, w0hh, 3*HH*HH/4);
  k_tobf16<<<(3*HH*HH/4+255)/256, 256>>>(g1wih, w1ih, 3*HH*HH/4);
  k_tobf16<<<(3*HH*HH/4+255)/256, 256>>>(g1whh, w1hh, 3*HH*HH/4);
  k_wsT<<<dim3(512, 4), 256>>>(enf8, waWw, aWb, Wsf8);
  k_mmT<<<dim3(92, 12, 1), 256>>>(xs, 512, w0ih, 1024, 512,
                                  xs, 512, w0ih, 1024, 512,
                                  1, 512, xg, 3*HH);

  auto attn_fc = [&](const float* h1cur, float* yout){
    k_mmT<<<dim3(4, 4, 2), 256>>>(h1cur, HH, waUw, 512, 0,
                                  h1cur, HH, waUw, 512, 0,
                                  2, 256, Up, HH);
    k_attn<<<BB, 256>>>(Wsf8, enf8, UP[0], UP[1], aUb, avw, avb, ctx);
    k_mmT<<<dim3(4, 4, 4), 256>>>(ctx, CC, wfcw, 1024, 0,
                                  h1cur, HH, wfcw, 1024, 512,
                                  2, 256, fp, HH);
    k_pwfc<<<BH/256, 256>>>(FP[0], FP[1], FP[2], FP[3], fcb, yout);
  };

  // y0 on main
  attn_fc(h1b, y0);

  // fork sB: h-recurrent gate halves for t=0
  cudaEventRecord(evFork, 0);
  cudaStreamWaitEvent(sB, evFork, 0);
  k_mmT<<<dim3(4, 12, 2), 256, 0, sB>>>(h0b, HH, w0hh, 512, 0,
                                        h0b, HH, w0hh, 512, 0,
                                        2, 256, GP0[2], 3*HH);
  cudaEventRecord(ev0h, sB);
  k_mmT<<<dim3(4, 12, 2), 256, 0, sB>>>(h1b, HH, w1hh, 512, 0,
                                        h1b, HH, w1hh, 512, 0,
                                        2, 256, GP1[2], 3*HH);
  cudaEventRecord(ev1h, sB);

  const float* yprev = y0;
  for (int t = 0; t < TT; t++){
    float* h0r = h0b + (size_t)(t & 1)*BH;
    float* h0w = h0b + (size_t)((t+1) & 1)*BH;
    float* h1r = h1b + (size_t)(t & 1)*BH;
    float* h1w = h1b + (size_t)((t+1) & 1)*BH;

    // GRU0 input half (critical path)
    k_mmT<<<dim3(4, 12, 2), 256>>>(yprev, HH, w0ih, 1024, 0,
                                   yprev, HH, w0ih, 1024, 0,
                                   2, 256, GP0[0], 3*HH);
    cudaStreamWaitEvent(0, ev0h, 0);
    k_pw<<<BH/256, 256>>>(GP0[0], GP0[1], GP0[2], GP0[3],
                          xg + (size_t)t*GSZ, h0r, g0bih, g0bhh, h0w);
    if (t+1 < TT){
      cudaEventRecord(evpw0, 0);
      cudaStreamWaitEvent(sB, evpw0, 0);
      k_mmT<<<dim3(4, 12, 2), 256, 0, sB>>>(h0w, HH, w0hh, 512, 0,
                                            h0w, HH, w0hh, 512, 0,
                                            2, 256, GP0[2], 3*HH);
      cudaEventRecord(ev0h, sB);
    }

    // GRU1 input half
    k_mmT<<<dim3(4, 12, 2), 256>>>(h0w, HH, w1ih, 512, 0,
                                   h0w, HH, w1ih, 512, 0,
                                   2, 256, GP1[0], 3*HH);
    cudaStreamWaitEvent(0, ev1h, 0);
    k_pw<<<BH/256, 256>>>(GP1[0], GP1[1], GP1[2], GP1[3],
                          (const float*)nullptr, h1r, g1bih, g1bhh, h1w);
    if (t+1 < TT){
      cudaEventRecord(evpw1, 0);
      cudaStreamWaitEvent(sB, evpw1, 0);
      k_mmT<<<dim3(4, 12, 2), 256, 0, sB>>>(h1w, HH, w1hh, 512, 0,
                                            h1w, HH, w1hh, 512, 0,
                                            2, 256, GP1[2], 3*HH);
      cudaEventRecord(ev1h, sB);
    }

    // attention + out_proj (main)
    attn_fc(h1w, ys + (size_t)t*BH);
    yprev = ys + (size_t)t*BH;
  }

  // logits (bf16 mma, fused bias) + NLL + reduce
  k_gl<<<92, 256>>>(ys, clsw, clsb, lgt);
  k_nll<<<NTOK/256, 256>>>(lgt, seq, nll, msk);
  k_reduce<<<1, 256>>>(nll, msk, (float*)d_out);
}